// round 11
// baseline (speedup 1.0000x reference)
#include <cuda_runtime.h>
#include <cuda_fp16.h>
#include <cstdint>
#include <cstddef>
#include <math.h>

#define N_NODES 100000
#define N_EDGES 1600000
#define N_POS   200000
#define N_NEG   200000
#define IN_C    128
#define HID_C   128
#define OUT_C   64
#define BN_EPS  1e-5f

// ---------------- scratch (static device globals; no allocation) ----------------
__device__ __half g_yh[N_NODES * 256];    // gathered features (fp16): yl / P|Q
__device__ __half g_yrh[N_NODES * 128];   // root-transform features (fp16)
__device__ __half g_hA[N_NODES * HID_C];  // hidden after layer 1 (fp16); reused as z_fp16
__device__ __half g_hB[N_NODES * HID_C];  // hidden after layer 2 (fp16)
__device__ __half g_wth[4 * 256 * 128];   // packed fp16 weight panels
__device__ int    g_count[N_NODES];       // zero at start of every execution (see k_decode2)
__device__ int    g_off[N_NODES];
__device__ int    g_cur[N_NODES];
__device__ int    g_part[256];
__device__ int    g_srcs[N_EDGES];

// Packed panel offsets (MUST match k_prep_count's layout!)
#define WT1_OFF 0          // Wl1|Wr1: 256x128
#define WT2_OFF 32768      // Wl2|Wr2: 256x128
#define WT3_OFF 65536      // Wl3|Wr3: 128x128
#define WT4_OFF 81920      // We1 top|bottom: 256x64
#define PREP_TOT 98304

// ------------- fused prep + count: weight panels + degree histogram -------------
// g_count must be all-zero on entry: guaranteed by initial static zero + the
// zeroing tail in k_decode2 at the end of every execution (replay-idempotent).
__global__ void k_prep_count(const int* __restrict__ dst,
                             const float* __restrict__ Wl1, const float* __restrict__ Wr1,
                             const float* __restrict__ Wl2, const float* __restrict__ Wr2,
                             const float* __restrict__ Wl3, const float* __restrict__ Wr3,
                             const float* __restrict__ We1) {
    int i = blockIdx.x * 256 + threadIdx.x;
    if (i < N_EDGES) atomicAdd(&g_count[dst[i]], 1);
    if (i >= PREP_TOT) return;
    float v;
    if (i < WT3_OFF) {
        const float* s1 = (i < WT2_OFF) ? Wl1 : Wl2;
        const float* s2 = (i < WT2_OFF) ? Wr1 : Wr2;
        int j = i & 32767;
        int mm = j >> 7, kk = j & 127;
        v = (mm < 128) ? s1[(size_t)kk * 128 + mm] : s2[(size_t)kk * 128 + (mm - 128)];
    } else if (i < WT4_OFF) {
        int j = i - WT3_OFF;                   // K=128, Mh=64
        int mm = j >> 7, kk = j & 127;
        v = (mm < 64) ? Wl3[(size_t)kk * 64 + mm] : Wr3[(size_t)kk * 64 + (mm - 64)];
    } else {
        int j = i - WT4_OFF;                   // K=64, Mh=128
        int mm = j >> 6, kk = j & 63;
        const float* s1 = We1;
        const float* s2 = We1 + 64 * 128;
        v = (mm < 128) ? s1[(size_t)kk * 128 + mm] : s2[(size_t)kk * 128 + (mm - 128)];
    }
    g_wth[i] = __float2half_rn(v);
}

// ---------------- CSR scan ----------------
__global__ void k_scan1() {
    __shared__ int sm[1024];
    int i = blockIdx.x * 1024 + threadIdx.x;
    int v = (i < N_NODES) ? g_count[i] : 0;
    sm[threadIdx.x] = v;
    __syncthreads();
    #pragma unroll
    for (int s = 1; s < 1024; s <<= 1) {
        int t = (threadIdx.x >= s) ? sm[threadIdx.x - s] : 0;
        __syncthreads();
        sm[threadIdx.x] += t;
        __syncthreads();
    }
    if (i < N_NODES) g_off[i] = sm[threadIdx.x] - v;
    if (threadIdx.x == 1023) g_part[blockIdx.x] = sm[1023];
}
__global__ void k_scan3() {
    __shared__ int red[32];
    int t = threadIdx.x, b = blockIdx.x;
    int v = (t < b) ? g_part[t] : 0;   // b <= 97 < 1024
    #pragma unroll
    for (int o = 16; o; o >>= 1) v += __shfl_xor_sync(0xFFFFFFFFu, v, o);
    if ((t & 31) == 0) red[t >> 5] = v;
    __syncthreads();
    if (t == 0) {
        int s = 0;
        #pragma unroll
        for (int w = 0; w < 32; w++) s += red[w];
        red[0] = s;
    }
    __syncthreads();
    int base = red[0];
    int i = b * 1024 + t;
    if (i < N_NODES) {
        int o = g_off[i] + base;
        g_off[i] = o;
        g_cur[i] = o;
    }
}
__global__ void k_fill(const int* __restrict__ src, const int* __restrict__ dst) {
    int i = blockIdx.x * blockDim.x + threadIdx.x;
    if (i < N_EDGES) {
        int d = dst[i];
        int p = atomicAdd(&g_cur[d], 1);
        g_srcs[p] = src[i];
    }
}

// ======== fp16 mma.sync m16n8k16 GEMM, 128x256 tile, 512 threads ========
// C[Nrows, 256] = A[Nrows, K] @ Wt[256, K]^T, fp32 accumulate, fp16 epilogue.
// cols < SPLIT -> o1 (stride S1); cols >= SPLIT -> o2 (stride S2).
template<int K, typename AT>
__global__ __launch_bounds__(512, 1) void k_mma256(const AT* __restrict__ A,
                                                   const __half* __restrict__ Wt,
                                                   __half* __restrict__ o1, int S1, int SPLIT,
                                                   __half* __restrict__ o2, int S2,
                                                   int Nrows) {
    constexpr int SA = K + 8;
    extern __shared__ __half sh[];
    __half* As = sh;                     // [128][SA]
    __half* Bs = sh + 128 * SA;          // [256][SA]

    const int tid  = threadIdx.x;
    const int lane = tid & 31, wid = tid >> 5;        // wid 0..15
    const int gid  = lane >> 2, tg = lane & 3;
    const int mrow = (wid & 3) * 32;                  // 0..96
    const int ncol = (wid >> 2) * 64;                 // 0..192
    const int row0 = blockIdx.x * 128;

    if (sizeof(AT) == 4) {
        // fp32 A: 128*(K/4) float4 total, K/16 per thread
        #pragma unroll
        for (int l = 0; l < K / 16; l++) {
            int f = tid + l * 512;
            int r = f / (K / 4), c4 = f % (K / 4);
            int grow = row0 + r;
            float4 v = make_float4(0.f, 0.f, 0.f, 0.f);
            if (grow < Nrows) v = *(const float4*)((const float*)A + (size_t)grow * K + c4 * 4);
            __half2 h0 = __floats2half2_rn(v.x, v.y);
            __half2 h1 = __floats2half2_rn(v.z, v.w);
            uint2 u;
            u.x = *(uint32_t*)&h0;
            u.y = *(uint32_t*)&h1;
            *(uint2*)(As + r * SA + c4 * 4) = u;
        }
    } else {
        // fp16 A: 128*(K/8) uint4 total, K/32 per thread
        #pragma unroll
        for (int l = 0; l < K / 32; l++) {
            int f = tid + l * 512;
            int r = f / (K / 8), c8 = f % (K / 8);
            int grow = row0 + r;
            uint4 v = make_uint4(0u, 0u, 0u, 0u);
            if (grow < Nrows) v = *(const uint4*)((const __half*)A + (size_t)grow * K + c8 * 8);
            *(uint4*)(As + r * SA + c8 * 8) = v;
        }
    }
    // B: 256 rows x K halves, pure copy: 256*(K/8) uint4, K/16 per thread
    #pragma unroll
    for (int l = 0; l < K / 16; l++) {
        int f = tid + l * 512;
        int r = f / (K / 8), c8 = f % (K / 8);
        uint4 v = *(const uint4*)(Wt + (size_t)r * K + c8 * 8);
        *(uint4*)(Bs + r * SA + c8 * 8) = v;
    }
    __syncthreads();

    float c[2][8][4];
    #pragma unroll
    for (int mt = 0; mt < 2; mt++)
        #pragma unroll
        for (int nt = 0; nt < 8; nt++)
            #pragma unroll
            for (int j = 0; j < 4; j++) c[mt][nt][j] = 0.f;

    #pragma unroll
    for (int ks = 0; ks < K / 16; ks++) {
        const int k0 = ks * 16;
        uint32_t a[2][4];
        #pragma unroll
        for (int mt = 0; mt < 2; mt++) {
            int r = mrow + mt * 16 + gid;
            a[mt][0] = *(const uint32_t*)(As + r * SA + k0 + 2 * tg);
            a[mt][1] = *(const uint32_t*)(As + (r + 8) * SA + k0 + 2 * tg);
            a[mt][2] = *(const uint32_t*)(As + r * SA + k0 + 8 + 2 * tg);
            a[mt][3] = *(const uint32_t*)(As + (r + 8) * SA + k0 + 8 + 2 * tg);
        }
        uint32_t b[8][2];
        #pragma unroll
        for (int nt = 0; nt < 8; nt++) {
            int rn = ncol + nt * 8 + gid;
            b[nt][0] = *(const uint32_t*)(Bs + rn * SA + k0 + 2 * tg);
            b[nt][1] = *(const uint32_t*)(Bs + rn * SA + k0 + 8 + 2 * tg);
        }
        #pragma unroll
        for (int mt = 0; mt < 2; mt++)
            #pragma unroll
            for (int nt = 0; nt < 8; nt++)
                asm volatile(
                    "mma.sync.aligned.m16n8k16.row.col.f32.f16.f16.f32 "
                    "{%0,%1,%2,%3}, {%4,%5,%6,%7}, {%8,%9}, {%0,%1,%2,%3};"
                    : "+f"(c[mt][nt][0]), "+f"(c[mt][nt][1]),
                      "+f"(c[mt][nt][2]), "+f"(c[mt][nt][3])
                    : "r"(a[mt][0]), "r"(a[mt][1]), "r"(a[mt][2]), "r"(a[mt][3]),
                      "r"(b[nt][0]), "r"(b[nt][1]));
    }

    #pragma unroll
    for (int mt = 0; mt < 2; mt++) {
        int r0 = row0 + mrow + mt * 16 + gid;
        int r1 = r0 + 8;
        #pragma unroll
        for (int nt = 0; nt < 8; nt++) {
            int colg = ncol + nt * 8 + 2 * tg;
            __half2 v0 = __halves2half2(__float2half_rn(c[mt][nt][0]), __float2half_rn(c[mt][nt][1]));
            __half2 v1 = __halves2half2(__float2half_rn(c[mt][nt][2]), __float2half_rn(c[mt][nt][3]));
            if (colg < SPLIT) {
                if (r0 < Nrows) *(__half2*)(o1 + (size_t)r0 * S1 + colg) = v0;
                if (r1 < Nrows) *(__half2*)(o1 + (size_t)r1 * S1 + colg) = v1;
            } else {
                int cf = colg - SPLIT;
                if (r0 < Nrows) *(__half2*)(o2 + (size_t)r0 * S2 + cf) = v0;
                if (r1 < Nrows) *(__half2*)(o2 + (size_t)r1 * S2 + cf) = v1;
            }
        }
    }
}

// ======== fp16 mma.sync 128x128 tile (layer 3, NOUT=128) ========
template<int K, typename AT>
__global__ __launch_bounds__(256, 2) void k_mma(const AT* __restrict__ A,
                                                const __half* __restrict__ Wt,
                                                __half* __restrict__ o1, int S1, int SPLIT,
                                                __half* __restrict__ o2, int S2,
                                                int Nrows) {
    constexpr int SA = K + 8;
    extern __shared__ __half sh[];
    __half* As = sh;                     // [128][SA]
    __half* Bs = sh + 128 * SA;          // [128][SA]

    const int tid  = threadIdx.x;
    const int lane = tid & 31, wid = tid >> 5;
    const int gid  = lane >> 2, tg = lane & 3;
    const int mrow = (wid & 3) * 32;
    const int ncol = (wid >> 2) * 64;
    const int row0 = blockIdx.x * 128;

    if (sizeof(AT) == 4) {
        #pragma unroll
        for (int l = 0; l < K / 8; l++) {
            int f = tid + l * 256;
            int r = f / (K / 4), c4 = f % (K / 4);
            int grow = row0 + r;
            float4 v = make_float4(0.f, 0.f, 0.f, 0.f);
            if (grow < Nrows) v = *(const float4*)((const float*)A + (size_t)grow * K + c4 * 4);
            __half2 h0 = __floats2half2_rn(v.x, v.y);
            __half2 h1 = __floats2half2_rn(v.z, v.w);
            uint2 u;
            u.x = *(uint32_t*)&h0;
            u.y = *(uint32_t*)&h1;
            *(uint2*)(As + r * SA + c4 * 4) = u;
        }
    } else {
        #pragma unroll
        for (int l = 0; l < K / 16; l++) {
            int f = tid + l * 256;
            int r = f / (K / 8), c8 = f % (K / 8);
            int grow = row0 + r;
            uint4 v = make_uint4(0u, 0u, 0u, 0u);
            if (grow < Nrows) v = *(const uint4*)((const __half*)A + (size_t)grow * K + c8 * 8);
            *(uint4*)(As + r * SA + c8 * 8) = v;
        }
    }
    #pragma unroll
    for (int l = 0; l < K / 16; l++) {
        int f = tid + l * 256;
        int r = f / (K / 8), c8 = f % (K / 8);
        uint4 v = *(const uint4*)(Wt + (size_t)r * K + c8 * 8);
        *(uint4*)(Bs + r * SA + c8 * 8) = v;
    }
    __syncthreads();

    float c[2][8][4];
    #pragma unroll
    for (int mt = 0; mt < 2; mt++)
        #pragma unroll
        for (int nt = 0; nt < 8; nt++)
            #pragma unroll
            for (int j = 0; j < 4; j++) c[mt][nt][j] = 0.f;

    #pragma unroll
    for (int ks = 0; ks < K / 16; ks++) {
        const int k0 = ks * 16;
        uint32_t a[2][4];
        #pragma unroll
        for (int mt = 0; mt < 2; mt++) {
            int r = mrow + mt * 16 + gid;
            a[mt][0] = *(const uint32_t*)(As + r * SA + k0 + 2 * tg);
            a[mt][1] = *(const uint32_t*)(As + (r + 8) * SA + k0 + 2 * tg);
            a[mt][2] = *(const uint32_t*)(As + r * SA + k0 + 8 + 2 * tg);
            a[mt][3] = *(const uint32_t*)(As + (r + 8) * SA + k0 + 8 + 2 * tg);
        }
        uint32_t b[8][2];
        #pragma unroll
        for (int nt = 0; nt < 8; nt++) {
            int rn = ncol + nt * 8 + gid;
            b[nt][0] = *(const uint32_t*)(Bs + rn * SA + k0 + 2 * tg);
            b[nt][1] = *(const uint32_t*)(Bs + rn * SA + k0 + 8 + 2 * tg);
        }
        #pragma unroll
        for (int mt = 0; mt < 2; mt++)
            #pragma unroll
            for (int nt = 0; nt < 8; nt++)
                asm volatile(
                    "mma.sync.aligned.m16n8k16.row.col.f32.f16.f16.f32 "
                    "{%0,%1,%2,%3}, {%4,%5,%6,%7}, {%8,%9}, {%0,%1,%2,%3};"
                    : "+f"(c[mt][nt][0]), "+f"(c[mt][nt][1]),
                      "+f"(c[mt][nt][2]), "+f"(c[mt][nt][3])
                    : "r"(a[mt][0]), "r"(a[mt][1]), "r"(a[mt][2]), "r"(a[mt][3]),
                      "r"(b[nt][0]), "r"(b[nt][1]));
    }

    #pragma unroll
    for (int mt = 0; mt < 2; mt++) {
        int r0 = row0 + mrow + mt * 16 + gid;
        int r1 = r0 + 8;
        #pragma unroll
        for (int nt = 0; nt < 8; nt++) {
            int colg = ncol + nt * 8 + 2 * tg;
            __half2 v0 = __halves2half2(__float2half_rn(c[mt][nt][0]), __float2half_rn(c[mt][nt][1]));
            __half2 v1 = __halves2half2(__float2half_rn(c[mt][nt][2]), __float2half_rn(c[mt][nt][3]));
            if (colg < SPLIT) {
                if (r0 < Nrows) *(__half2*)(o1 + (size_t)r0 * S1 + colg) = v0;
                if (r1 < Nrows) *(__half2*)(o1 + (size_t)r1 * S1 + colg) = v1;
            } else {
                int cf = colg - SPLIT;
                if (r0 < Nrows) *(__half2*)(o2 + (size_t)r0 * S2 + cf) = v0;
                if (r1 < Nrows) *(__half2*)(o2 + (size_t)r1 * S2 + cf) = v1;
            }
        }
    }
}

// ---------------- fused aggregation + combine (warp per node, fp16 gather) ------
// RES: 0 = no BN/ReLU/residual: writes outF (fp32 z) AND outH (fp16 z copy)
//      1 = fp32 residual -> outH ; 2 = fp16 residual -> outH
template<int C, int RES>
__global__ __launch_bounds__(256) void k_aggh(const float* __restrict__ bl,
                                              const float* __restrict__ gam,
                                              const float* __restrict__ bet,
                                              const float* __restrict__ hinF,
                                              const __half* __restrict__ hinH,
                                              __half* __restrict__ outH,
                                              float* __restrict__ outF,
                                              const __half* __restrict__ yh,
                                              const __half* __restrict__ yrh) {
    constexpr int V = C / 32;
    int warp = (blockIdx.x * 256 + threadIdx.x) >> 5;
    int lane = threadIdx.x & 31;
    if (warp >= N_NODES) return;
    int n = warp;
    int beg = g_off[n], cnt = g_count[n];

    float acc[V];
    #pragma unroll
    for (int j = 0; j < V; j++) acc[j] = 0.f;

    for (int e0 = 0; e0 < cnt; e0 += 32) {
        int m = min(32, cnt - e0);
        int myidx = (lane < m) ? __ldg(&g_srcs[beg + e0 + lane]) : 0;
        int i = 0;
        for (; i + 4 <= m; i += 4) {
            int s0 = __shfl_sync(0xFFFFFFFFu, myidx, i);
            int s1 = __shfl_sync(0xFFFFFFFFu, myidx, i + 1);
            int s2 = __shfl_sync(0xFFFFFFFFu, myidx, i + 2);
            int s3 = __shfl_sync(0xFFFFFFFFu, myidx, i + 3);
            if (V == 4) {
                uint2 u0 = *(const uint2*)(yh + (size_t)s0 * C + lane * 4);
                uint2 u1 = *(const uint2*)(yh + (size_t)s1 * C + lane * 4);
                uint2 u2 = *(const uint2*)(yh + (size_t)s2 * C + lane * 4);
                uint2 u3 = *(const uint2*)(yh + (size_t)s3 * C + lane * 4);
                float2 a0 = __half22float2(*(__half2*)&u0.x), b0 = __half22float2(*(__half2*)&u0.y);
                float2 a1 = __half22float2(*(__half2*)&u1.x), b1 = __half22float2(*(__half2*)&u1.y);
                float2 a2 = __half22float2(*(__half2*)&u2.x), b2 = __half22float2(*(__half2*)&u2.y);
                float2 a3 = __half22float2(*(__half2*)&u3.x), b3 = __half22float2(*(__half2*)&u3.y);
                acc[0] += a0.x + a1.x + a2.x + a3.x;
                acc[1] += a0.y + a1.y + a2.y + a3.y;
                acc[2] += b0.x + b1.x + b2.x + b3.x;
                acc[3] += b0.y + b1.y + b2.y + b3.y;
            } else {
                uint32_t u0 = *(const uint32_t*)(yh + (size_t)s0 * C + lane * 2);
                uint32_t u1 = *(const uint32_t*)(yh + (size_t)s1 * C + lane * 2);
                uint32_t u2 = *(const uint32_t*)(yh + (size_t)s2 * C + lane * 2);
                uint32_t u3 = *(const uint32_t*)(yh + (size_t)s3 * C + lane * 2);
                float2 a0 = __half22float2(*(__half2*)&u0);
                float2 a1 = __half22float2(*(__half2*)&u1);
                float2 a2 = __half22float2(*(__half2*)&u2);
                float2 a3 = __half22float2(*(__half2*)&u3);
                acc[0] += a0.x + a1.x + a2.x + a3.x;
                acc[1] += a0.y + a1.y + a2.y + a3.y;
            }
        }
        for (; i < m; i++) {
            int s = __shfl_sync(0xFFFFFFFFu, myidx, i);
            if (V == 4) {
                uint2 u = *(const uint2*)(yh + (size_t)s * C + lane * 4);
                float2 a = __half22float2(*(__half2*)&u.x), b = __half22float2(*(__half2*)&u.y);
                acc[0] += a.x; acc[1] += a.y; acc[2] += b.x; acc[3] += b.y;
            } else {
                uint32_t u = *(const uint32_t*)(yh + (size_t)s * C + lane * 2);
                float2 a = __half22float2(*(__half2*)&u);
                acc[0] += a.x; acc[1] += a.y;
            }
        }
    }
    float inv = 1.0f / fmaxf((float)cnt, 1.0f);

    float o[V];
    {
        if (V == 4) {
            uint2 u = *(const uint2*)(yrh + (size_t)n * C + lane * 4);
            float2 a = __half22float2(*(__half2*)&u.x), b = __half22float2(*(__half2*)&u.y);
            o[0] = acc[0] * inv + bl[lane * 4 + 0] + a.x;
            o[1] = acc[1] * inv + bl[lane * 4 + 1] + a.y;
            o[2] = acc[2] * inv + bl[lane * 4 + 2] + b.x;
            o[3] = acc[3] * inv + bl[lane * 4 + 3] + b.y;
        } else {
            uint32_t u = *(const uint32_t*)(yrh + (size_t)n * C + lane * 2);
            float2 a = __half22float2(*(__half2*)&u);
            o[0] = acc[0] * inv + bl[lane * 2 + 0] + a.x;
            o[1] = acc[1] * inv + bl[lane * 2 + 1] + a.y;
        }
    }
    if (RES != 0) {
        const float s = rsqrtf(1.0f + BN_EPS);
        float h[V];
        if (RES == 1) {
            const float* hp = hinF + (size_t)n * C + lane * V;
            #pragma unroll
            for (int j = 0; j < V; j++) h[j] = hp[j];
        } else {
            uint2 u = *(const uint2*)(hinH + (size_t)n * C + lane * 4);
            float2 a = __half22float2(*(__half2*)&u.x), b = __half22float2(*(__half2*)&u.y);
            h[0] = a.x; h[1] = a.y; h[2] = b.x; h[3] = b.y;
        }
        #pragma unroll
        for (int j = 0; j < V; j++) {
            int ch = lane * V + j;
            o[j] = fmaxf(o[j] * (gam[ch] * s) + bet[ch], 0.f) + h[j];
        }
        if (V == 4) {
            __half2 h0 = __floats2half2_rn(o[0], o[1]);
            __half2 h1 = __floats2half2_rn(o[2], o[3]);
            uint2 u;
            u.x = *(uint32_t*)&h0;
            u.y = *(uint32_t*)&h1;
            *(uint2*)(outH + (size_t)n * C + lane * 4) = u;
        } else {
            __half2 h0 = __floats2half2_rn(o[0], o[1]);
            *(uint32_t*)(outH + (size_t)n * C + lane * 2) = *(uint32_t*)&h0;
        }
    } else {
        // fp32 z output + fp16 z copy (feeds fp16 decode GEMM)
        if (V == 4) {
            *(float4*)(outF + (size_t)n * C + lane * 4) = make_float4(o[0], o[1], o[2], o[3]);
            __half2 h0 = __floats2half2_rn(o[0], o[1]);
            __half2 h1 = __floats2half2_rn(o[2], o[3]);
            uint2 u;
            u.x = *(uint32_t*)&h0;
            u.y = *(uint32_t*)&h1;
            *(uint2*)(outH + (size_t)n * C + lane * 4) = u;
        } else {
            *(float2*)(outF + (size_t)n * C + lane * 2) = make_float2(o[0], o[1]);
            __half2 h0 = __floats2half2_rn(o[0], o[1]);
            *(uint32_t*)(outH + (size_t)n * C + lane * 2) = *(uint32_t*)&h0;
        }
    }
}

// ---------------- merged edge decode (pos + neg) + g_count reset ---------------
__global__ void k_decode2(const int* __restrict__ pos, const int* __restrict__ neg,
                          const float* __restrict__ be1,
                          const float* __restrict__ We2, const float* __restrict__ be2,
                          float* __restrict__ outpos, float* __restrict__ outneg,
                          const __half* __restrict__ yh) {
    int gidx = blockIdx.x * blockDim.x + threadIdx.x;
    if (gidx < N_NODES) g_count[gidx] = 0;   // reset for next execution (replay-idempotent)
    int warp = gidx >> 5;
    int lane = threadIdx.x & 31;
    if (warp >= N_POS + N_NEG) return;
    int s, d;
    float* op;
    if (warp < N_POS) {
        s = pos[warp]; d = pos[N_POS + warp]; op = outpos + warp;
    } else {
        int w = warp - N_POS;
        s = neg[w]; d = neg[N_NEG + w]; op = outneg + w;
    }
    uint2 up = *(const uint2*)(yh + (size_t)s * 256 + lane * 4);
    uint2 uq = *(const uint2*)(yh + (size_t)d * 256 + 128 + lane * 4);
    float2 p0 = __half22float2(*(__half2*)&up.x), p1 = __half22float2(*(__half2*)&up.y);
    float2 q0 = __half22float2(*(__half2*)&uq.x), q1 = __half22float2(*(__half2*)&uq.y);
    float4 bb = *(const float4*)(be1 + lane * 4);
    float4 w  = *(const float4*)(We2 + lane * 4);
    float sum = fmaxf(p0.x + q0.x + bb.x, 0.f) * w.x
              + fmaxf(p0.y + q0.y + bb.y, 0.f) * w.y
              + fmaxf(p1.x + q1.x + bb.z, 0.f) * w.z
              + fmaxf(p1.y + q1.y + bb.w, 0.f) * w.w;
    #pragma unroll
    for (int o = 16; o; o >>= 1) sum += __shfl_xor_sync(0xFFFFFFFFu, sum, o);
    if (lane == 0) *op = 1.0f / (1.0f + expf(-(sum + be2[0])));
}

// ---------------- host launcher ----------------
extern "C" void kernel_launch(void* const* d_in, const int* in_sizes, int n_in,
                              void* d_out, int out_size) {
    const float* x   = (const float*)d_in[0];
    const int*   ei  = (const int*)d_in[1];
    const int*   pos = (const int*)d_in[2];
    const int*   neg = (const int*)d_in[3];
    const float* Wl1 = (const float*)d_in[4];
    const float* bl1 = (const float*)d_in[5];
    const float* Wr1 = (const float*)d_in[6];
    const float* g1  = (const float*)d_in[7];
    const float* b1  = (const float*)d_in[8];
    const float* Wl2 = (const float*)d_in[9];
    const float* bl2 = (const float*)d_in[10];
    const float* Wr2 = (const float*)d_in[11];
    const float* g2  = (const float*)d_in[12];
    const float* b2  = (const float*)d_in[13];
    const float* Wl3 = (const float*)d_in[14];
    const float* bl3 = (const float*)d_in[15];
    const float* Wr3 = (const float*)d_in[16];
    const float* We1 = (const float*)d_in[17];
    const float* be1 = (const float*)d_in[18];
    const float* We2 = (const float*)d_in[19];
    const float* be2 = (const float*)d_in[20];

    float* out    = (float*)d_out;
    float* z      = out;
    float* outpos = out + (size_t)N_NODES * OUT_C;
    float* outneg = outpos + N_POS;

    __half *yh, *yrh, *hA, *hB, *wt;
    cudaGetSymbolAddress((void**)&yh, g_yh);
    cudaGetSymbolAddress((void**)&yrh, g_yrh);
    cudaGetSymbolAddress((void**)&hA, g_hA);
    cudaGetSymbolAddress((void**)&hB, g_hB);
    cudaGetSymbolAddress((void**)&wt, g_wth);
    __half* wt1 = wt + WT1_OFF;
    __half* wt2 = wt + WT2_OFF;
    __half* wt3 = wt + WT3_OFF;
    __half* wt4 = wt + WT4_OFF;

    const int SM256_128 = (128 + 256) * (128 + 8) * 2;  // 104448
    const int SM256_64  = (128 + 256) * (64 + 8) * 2;   //  55296
    const int SM128     = 2 * 128 * (128 + 8) * 2;      //  69632
    cudaFuncSetAttribute(k_mma256<128, float>,  cudaFuncAttributeMaxDynamicSharedMemorySize, SM256_128);
    cudaFuncSetAttribute(k_mma256<128, __half>, cudaFuncAttributeMaxDynamicSharedMemorySize, SM256_128);
    cudaFuncSetAttribute(k_mma256<64, __half>,  cudaFuncAttributeMaxDynamicSharedMemorySize, SM256_64);
    cudaFuncSetAttribute(k_mma<128, __half>,    cudaFuncAttributeMaxDynamicSharedMemorySize, SM128);

    const int EB = (N_EDGES + 255) / 256;
    const int SCAN_NB = (N_NODES + 1023) / 1024;
    const int GT = (N_NODES + 127) / 128;
    const int AGGB = (N_NODES * 32 + 255) / 256;

    // ---- CSR build + weight prep (counts pre-zeroed by previous execution) ----
    k_prep_count<<<EB, 256>>>(ei + N_EDGES, Wl1, Wr1, Wl2, Wr2, Wl3, Wr3, We1);
    k_scan1<<<SCAN_NB, 1024>>>();
    k_scan3<<<SCAN_NB, 1024>>>();
    k_fill<<<EB, 256>>>(ei, ei + N_EDGES);

    // ---- layer 1: 128x256 tile; yl->yh, yr->yrh ----
    k_mma256<128, float><<<GT, 512, SM256_128>>>(x, wt1, yh, 128, 128, yrh, 128, N_NODES);
    k_aggh<128, 1><<<AGGB, 256>>>(bl1, g1, b1, x, nullptr, hA, nullptr, yh, yrh);

    // ---- layer 2 (fp16 input) ----
    k_mma256<128, __half><<<GT, 512, SM256_128>>>(hA, wt2, yh, 128, 128, yrh, 128, N_NODES);
    k_aggh<128, 2><<<AGGB, 256>>>(bl2, g2, b2, nullptr, hA, hB, nullptr, yh, yrh);

    // ---- layer 3 (NOUT=128, 128x128 tile); z fp32 -> d_out, z fp16 -> hA ----
    k_mma<128, __half><<<GT, 256, SM128>>>(hB, wt3, yh, 64, 64, yrh, 64, N_NODES);
    k_aggh<64, 0><<<AGGB, 256>>>(bl3, nullptr, nullptr, nullptr, nullptr, hA, z, yh, yrh);

    // ---- decode prep: P|Q from fp16 z ----
    k_mma256<64, __half><<<GT, 512, SM256_64>>>(hA, wt4, yh, 256, 256, nullptr, 0, N_NODES);

    // ---- decode (merged pos+neg, + count reset for next execution) ----
    k_decode2<<<((N_POS + N_NEG) * 32 + 127) / 128, 128>>>(pos, neg, be1, We2, be2, outpos, outneg, yh);
}

// round 12
// speedup vs baseline: 1.0330x; 1.0330x over previous
#include <cuda_runtime.h>
#include <cuda_fp16.h>
#include <cstdint>
#include <cstddef>
#include <math.h>

#define N_NODES 100000
#define N_EDGES 1600000
#define N_POS   200000
#define N_NEG   200000
#define IN_C    128
#define HID_C   128
#define OUT_C   64
#define BN_EPS  1e-5f

// ---------------- scratch (static device globals; no allocation) ----------------
__device__ __half g_yh[N_NODES * 256];    // gathered features (fp16): yl / P|Q
__device__ __half g_yrh[N_NODES * 128];   // root-transform features (fp16)
__device__ __half g_hA[N_NODES * HID_C];  // hidden after layer 1 (fp16); reused as z_fp16
__device__ __half g_hB[N_NODES * HID_C];  // hidden after layer 2 (fp16)
__device__ __half g_wth[4 * 256 * 128];   // packed fp16 weight panels
__device__ int    g_count[N_NODES];       // zero at entry (static init + k_decode2 tail)
__device__ int    g_off[N_NODES];
__device__ int    g_cur[N_NODES];
__device__ int    g_part[256];
__device__ int    g_srcs[N_EDGES];

// Packed panel offsets (MUST match k_prep_count's layout!)
#define WT1_OFF 0          // Wl1|Wr1: 256x128
#define WT2_OFF 32768      // Wl2|Wr2: 256x128
#define WT3_OFF 65536      // Wl3|Wr3: 128x128
#define WT4_OFF 81920      // We1 top|bottom: 256x64
#define PREP_TOT 98304

// ------------- fused prep + count: weight panels + degree histogram -------------
__global__ void k_prep_count(const int* __restrict__ dst,
                             const float* __restrict__ Wl1, const float* __restrict__ Wr1,
                             const float* __restrict__ Wl2, const float* __restrict__ Wr2,
                             const float* __restrict__ Wl3, const float* __restrict__ Wr3,
                             const float* __restrict__ We1) {
    int i = blockIdx.x * 256 + threadIdx.x;
    if (i < N_EDGES) atomicAdd(&g_count[dst[i]], 1);
    if (i >= PREP_TOT) return;
    float v;
    if (i < WT3_OFF) {
        const float* s1 = (i < WT2_OFF) ? Wl1 : Wl2;
        const float* s2 = (i < WT2_OFF) ? Wr1 : Wr2;
        int j = i & 32767;
        int mm = j >> 7, kk = j & 127;
        v = (mm < 128) ? s1[(size_t)kk * 128 + mm] : s2[(size_t)kk * 128 + (mm - 128)];
    } else if (i < WT4_OFF) {
        int j = i - WT3_OFF;                   // K=128, Mh=64
        int mm = j >> 7, kk = j & 127;
        v = (mm < 64) ? Wl3[(size_t)kk * 64 + mm] : Wr3[(size_t)kk * 64 + (mm - 64)];
    } else {
        int j = i - WT4_OFF;                   // K=64, Mh=128
        int mm = j >> 6, kk = j & 63;
        const float* s1 = We1;
        const float* s2 = We1 + 64 * 128;
        v = (mm < 128) ? s1[(size_t)kk * 128 + mm] : s2[(size_t)kk * 128 + (mm - 128)];
    }
    g_wth[i] = __float2half_rn(v);
}

// ---------------- CSR scan ----------------
__global__ void k_scan1() {
    __shared__ int sm[1024];
    int i = blockIdx.x * 1024 + threadIdx.x;
    int v = (i < N_NODES) ? g_count[i] : 0;
    sm[threadIdx.x] = v;
    __syncthreads();
    #pragma unroll
    for (int s = 1; s < 1024; s <<= 1) {
        int t = (threadIdx.x >= s) ? sm[threadIdx.x - s] : 0;
        __syncthreads();
        sm[threadIdx.x] += t;
        __syncthreads();
    }
    if (i < N_NODES) g_off[i] = sm[threadIdx.x] - v;
    if (threadIdx.x == 1023) g_part[blockIdx.x] = sm[1023];
}
__global__ void k_scan3() {
    __shared__ int red[32];
    int t = threadIdx.x, b = blockIdx.x;
    int v = (t < b) ? g_part[t] : 0;   // b <= 97 < 1024
    #pragma unroll
    for (int o = 16; o; o >>= 1) v += __shfl_xor_sync(0xFFFFFFFFu, v, o);
    if ((t & 31) == 0) red[t >> 5] = v;
    __syncthreads();
    if (t == 0) {
        int s = 0;
        #pragma unroll
        for (int w = 0; w < 32; w++) s += red[w];
        red[0] = s;
    }
    __syncthreads();
    int base = red[0];
    int i = b * 1024 + t;
    if (i < N_NODES) {
        int o = g_off[i] + base;
        g_off[i] = o;
        g_cur[i] = o;
    }
}
__global__ void k_fill(const int* __restrict__ src, const int* __restrict__ dst) {
    int i = blockIdx.x * blockDim.x + threadIdx.x;
    if (i < N_EDGES) {
        int d = dst[i];
        int p = atomicAdd(&g_cur[d], 1);
        g_srcs[p] = src[i];
    }
}

// ======== fp16 mma.sync m16n8k16 GEMM, 128x128 tile, 256 thr, 2 CTA/SM ========
// C[Nrows, NOUT] = A[Nrows, K] @ Wt[NOUT, K]^T; grid.y selects 128-col panel.
// cols < SPLIT -> o1 (stride S1); cols >= SPLIT -> o2 (stride S2). Both fp16.
template<int K, typename AT>
__global__ __launch_bounds__(256, 2) void k_mma(const AT* __restrict__ A,
                                                const __half* __restrict__ Wt,
                                                __half* __restrict__ o1, int S1, int SPLIT,
                                                __half* __restrict__ o2, int S2,
                                                int Nrows) {
    constexpr int SA = K + 8;
    extern __shared__ __half sh[];
    __half* As = sh;                     // [128][SA]
    __half* Bs = sh + 128 * SA;          // [128][SA]

    const int tid  = threadIdx.x;
    const int lane = tid & 31, wid = tid >> 5;
    const int gid  = lane >> 2, tg = lane & 3;
    const int mrow = (wid & 3) * 32;
    const int ncol = (wid >> 2) * 64;
    const int row0 = blockIdx.x * 128;
    const int col0 = blockIdx.y * 128;

    if (sizeof(AT) == 4) {
        #pragma unroll
        for (int l = 0; l < K / 8; l++) {
            int f = tid + l * 256;
            int r = f / (K / 4), c4 = f % (K / 4);
            int grow = row0 + r;
            float4 v = make_float4(0.f, 0.f, 0.f, 0.f);
            if (grow < Nrows) v = *(const float4*)((const float*)A + (size_t)grow * K + c4 * 4);
            __half2 h0 = __floats2half2_rn(v.x, v.y);
            __half2 h1 = __floats2half2_rn(v.z, v.w);
            uint2 u;
            u.x = *(uint32_t*)&h0;
            u.y = *(uint32_t*)&h1;
            *(uint2*)(As + r * SA + c4 * 4) = u;
        }
    } else {
        #pragma unroll
        for (int l = 0; l < K / 16; l++) {
            int f = tid + l * 256;
            int r = f / (K / 8), c8 = f % (K / 8);
            int grow = row0 + r;
            uint4 v = make_uint4(0u, 0u, 0u, 0u);
            if (grow < Nrows) v = *(const uint4*)((const __half*)A + (size_t)grow * K + c8 * 8);
            *(uint4*)(As + r * SA + c8 * 8) = v;
        }
    }
    // stage B: pure copy of this 128-col panel
    #pragma unroll
    for (int l = 0; l < K / 16; l++) {
        int f = tid + l * 256;
        int r = f / (K / 8), c8 = f % (K / 8);
        uint4 v = *(const uint4*)(Wt + (size_t)(col0 + r) * K + c8 * 8);
        *(uint4*)(Bs + r * SA + c8 * 8) = v;
    }
    __syncthreads();

    float c[2][8][4];
    #pragma unroll
    for (int mt = 0; mt < 2; mt++)
        #pragma unroll
        for (int nt = 0; nt < 8; nt++)
            #pragma unroll
            for (int j = 0; j < 4; j++) c[mt][nt][j] = 0.f;

    #pragma unroll
    for (int ks = 0; ks < K / 16; ks++) {
        const int k0 = ks * 16;
        uint32_t a[2][4];
        #pragma unroll
        for (int mt = 0; mt < 2; mt++) {
            int r = mrow + mt * 16 + gid;
            a[mt][0] = *(const uint32_t*)(As + r * SA + k0 + 2 * tg);
            a[mt][1] = *(const uint32_t*)(As + (r + 8) * SA + k0 + 2 * tg);
            a[mt][2] = *(const uint32_t*)(As + r * SA + k0 + 8 + 2 * tg);
            a[mt][3] = *(const uint32_t*)(As + (r + 8) * SA + k0 + 8 + 2 * tg);
        }
        uint32_t b[8][2];
        #pragma unroll
        for (int nt = 0; nt < 8; nt++) {
            int rn = ncol + nt * 8 + gid;
            b[nt][0] = *(const uint32_t*)(Bs + rn * SA + k0 + 2 * tg);
            b[nt][1] = *(const uint32_t*)(Bs + rn * SA + k0 + 8 + 2 * tg);
        }
        #pragma unroll
        for (int mt = 0; mt < 2; mt++)
            #pragma unroll
            for (int nt = 0; nt < 8; nt++)
                asm volatile(
                    "mma.sync.aligned.m16n8k16.row.col.f32.f16.f16.f32 "
                    "{%0,%1,%2,%3}, {%4,%5,%6,%7}, {%8,%9}, {%0,%1,%2,%3};"
                    : "+f"(c[mt][nt][0]), "+f"(c[mt][nt][1]),
                      "+f"(c[mt][nt][2]), "+f"(c[mt][nt][3])
                    : "r"(a[mt][0]), "r"(a[mt][1]), "r"(a[mt][2]), "r"(a[mt][3]),
                      "r"(b[nt][0]), "r"(b[nt][1]));
    }

    #pragma unroll
    for (int mt = 0; mt < 2; mt++) {
        int r0 = row0 + mrow + mt * 16 + gid;
        int r1 = r0 + 8;
        #pragma unroll
        for (int nt = 0; nt < 8; nt++) {
            int colg = col0 + ncol + nt * 8 + 2 * tg;
            __half2 v0 = __halves2half2(__float2half_rn(c[mt][nt][0]), __float2half_rn(c[mt][nt][1]));
            __half2 v1 = __halves2half2(__float2half_rn(c[mt][nt][2]), __float2half_rn(c[mt][nt][3]));
            if (colg < SPLIT) {
                if (r0 < Nrows) *(__half2*)(o1 + (size_t)r0 * S1 + colg) = v0;
                if (r1 < Nrows) *(__half2*)(o1 + (size_t)r1 * S1 + colg) = v1;
            } else {
                int cf = colg - SPLIT;
                if (r0 < Nrows) *(__half2*)(o2 + (size_t)r0 * S2 + cf) = v0;
                if (r1 < Nrows) *(__half2*)(o2 + (size_t)r1 * S2 + cf) = v1;
            }
        }
    }
}

// ---------------- fused aggregation + combine (warp per node, fp16 gather) ------
// RES: 0 = no BN/ReLU/residual: writes outF (fp32 z) AND outH (fp16 z copy)
//      1 = fp32 residual -> outH ; 2 = fp16 residual -> outH
template<int C, int RES>
__global__ __launch_bounds__(256) void k_aggh(const float* __restrict__ bl,
                                              const float* __restrict__ gam,
                                              const float* __restrict__ bet,
                                              const float* __restrict__ hinF,
                                              const __half* __restrict__ hinH,
                                              __half* __restrict__ outH,
                                              float* __restrict__ outF,
                                              const __half* __restrict__ yh,
                                              const __half* __restrict__ yrh) {
    constexpr int V = C / 32;
    int warp = (blockIdx.x * 256 + threadIdx.x) >> 5;
    int lane = threadIdx.x & 31;
    if (warp >= N_NODES) return;
    int n = warp;
    int beg = g_off[n], cnt = g_count[n];

    float acc[V];
    #pragma unroll
    for (int j = 0; j < V; j++) acc[j] = 0.f;

    for (int e0 = 0; e0 < cnt; e0 += 32) {
        int m = min(32, cnt - e0);
        int myidx = (lane < m) ? __ldg(&g_srcs[beg + e0 + lane]) : 0;
        int i = 0;
        for (; i + 4 <= m; i += 4) {
            int s0 = __shfl_sync(0xFFFFFFFFu, myidx, i);
            int s1 = __shfl_sync(0xFFFFFFFFu, myidx, i + 1);
            int s2 = __shfl_sync(0xFFFFFFFFu, myidx, i + 2);
            int s3 = __shfl_sync(0xFFFFFFFFu, myidx, i + 3);
            if (V == 4) {
                uint2 u0 = *(const uint2*)(yh + (size_t)s0 * C + lane * 4);
                uint2 u1 = *(const uint2*)(yh + (size_t)s1 * C + lane * 4);
                uint2 u2 = *(const uint2*)(yh + (size_t)s2 * C + lane * 4);
                uint2 u3 = *(const uint2*)(yh + (size_t)s3 * C + lane * 4);
                float2 a0 = __half22float2(*(__half2*)&u0.x), b0 = __half22float2(*(__half2*)&u0.y);
                float2 a1 = __half22float2(*(__half2*)&u1.x), b1 = __half22float2(*(__half2*)&u1.y);
                float2 a2 = __half22float2(*(__half2*)&u2.x), b2 = __half22float2(*(__half2*)&u2.y);
                float2 a3 = __half22float2(*(__half2*)&u3.x), b3 = __half22float2(*(__half2*)&u3.y);
                acc[0] += a0.x + a1.x + a2.x + a3.x;
                acc[1] += a0.y + a1.y + a2.y + a3.y;
                acc[2] += b0.x + b1.x + b2.x + b3.x;
                acc[3] += b0.y + b1.y + b2.y + b3.y;
            } else {
                uint32_t u0 = *(const uint32_t*)(yh + (size_t)s0 * C + lane * 2);
                uint32_t u1 = *(const uint32_t*)(yh + (size_t)s1 * C + lane * 2);
                uint32_t u2 = *(const uint32_t*)(yh + (size_t)s2 * C + lane * 2);
                uint32_t u3 = *(const uint32_t*)(yh + (size_t)s3 * C + lane * 2);
                float2 a0 = __half22float2(*(__half2*)&u0);
                float2 a1 = __half22float2(*(__half2*)&u1);
                float2 a2 = __half22float2(*(__half2*)&u2);
                float2 a3 = __half22float2(*(__half2*)&u3);
                acc[0] += a0.x + a1.x + a2.x + a3.x;
                acc[1] += a0.y + a1.y + a2.y + a3.y;
            }
        }
        for (; i < m; i++) {
            int s = __shfl_sync(0xFFFFFFFFu, myidx, i);
            if (V == 4) {
                uint2 u = *(const uint2*)(yh + (size_t)s * C + lane * 4);
                float2 a = __half22float2(*(__half2*)&u.x), b = __half22float2(*(__half2*)&u.y);
                acc[0] += a.x; acc[1] += a.y; acc[2] += b.x; acc[3] += b.y;
            } else {
                uint32_t u = *(const uint32_t*)(yh + (size_t)s * C + lane * 2);
                float2 a = __half22float2(*(__half2*)&u);
                acc[0] += a.x; acc[1] += a.y;
            }
        }
    }
    float inv = 1.0f / fmaxf((float)cnt, 1.0f);

    float o[V];
    {
        if (V == 4) {
            uint2 u = *(const uint2*)(yrh + (size_t)n * C + lane * 4);
            float2 a = __half22float2(*(__half2*)&u.x), b = __half22float2(*(__half2*)&u.y);
            o[0] = acc[0] * inv + bl[lane * 4 + 0] + a.x;
            o[1] = acc[1] * inv + bl[lane * 4 + 1] + a.y;
            o[2] = acc[2] * inv + bl[lane * 4 + 2] + b.x;
            o[3] = acc[3] * inv + bl[lane * 4 + 3] + b.y;
        } else {
            uint32_t u = *(const uint32_t*)(yrh + (size_t)n * C + lane * 2);
            float2 a = __half22float2(*(__half2*)&u);
            o[0] = acc[0] * inv + bl[lane * 2 + 0] + a.x;
            o[1] = acc[1] * inv + bl[lane * 2 + 1] + a.y;
        }
    }
    if (RES != 0) {
        const float s = rsqrtf(1.0f + BN_EPS);
        float h[V];
        if (RES == 1) {
            const float* hp = hinF + (size_t)n * C + lane * V;
            #pragma unroll
            for (int j = 0; j < V; j++) h[j] = hp[j];
        } else {
            uint2 u = *(const uint2*)(hinH + (size_t)n * C + lane * 4);
            float2 a = __half22float2(*(__half2*)&u.x), b = __half22float2(*(__half2*)&u.y);
            h[0] = a.x; h[1] = a.y; h[2] = b.x; h[3] = b.y;
        }
        #pragma unroll
        for (int j = 0; j < V; j++) {
            int ch = lane * V + j;
            o[j] = fmaxf(o[j] * (gam[ch] * s) + bet[ch], 0.f) + h[j];
        }
        if (V == 4) {
            __half2 h0 = __floats2half2_rn(o[0], o[1]);
            __half2 h1 = __floats2half2_rn(o[2], o[3]);
            uint2 u;
            u.x = *(uint32_t*)&h0;
            u.y = *(uint32_t*)&h1;
            *(uint2*)(outH + (size_t)n * C + lane * 4) = u;
        } else {
            __half2 h0 = __floats2half2_rn(o[0], o[1]);
            *(uint32_t*)(outH + (size_t)n * C + lane * 2) = *(uint32_t*)&h0;
        }
    } else {
        // fp32 z output + fp16 z copy (feeds fp16 decode GEMM)
        if (V == 4) {
            *(float4*)(outF + (size_t)n * C + lane * 4) = make_float4(o[0], o[1], o[2], o[3]);
            __half2 h0 = __floats2half2_rn(o[0], o[1]);
            __half2 h1 = __floats2half2_rn(o[2], o[3]);
            uint2 u;
            u.x = *(uint32_t*)&h0;
            u.y = *(uint32_t*)&h1;
            *(uint2*)(outH + (size_t)n * C + lane * 4) = u;
        } else {
            *(float2*)(outF + (size_t)n * C + lane * 2) = make_float2(o[0], o[1]);
            __half2 h0 = __floats2half2_rn(o[0], o[1]);
            *(uint32_t*)(outH + (size_t)n * C + lane * 2) = *(uint32_t*)&h0;
        }
    }
}

// ---------------- merged edge decode (pos + neg) + g_count reset ---------------
__global__ void k_decode2(const int* __restrict__ pos, const int* __restrict__ neg,
                          const float* __restrict__ be1,
                          const float* __restrict__ We2, const float* __restrict__ be2,
                          float* __restrict__ outpos, float* __restrict__ outneg,
                          const __half* __restrict__ yh) {
    int gidx = blockIdx.x * blockDim.x + threadIdx.x;
    if (gidx < N_NODES) g_count[gidx] = 0;   // reset for next execution (replay-idempotent)
    int warp = gidx >> 5;
    int lane = threadIdx.x & 31;
    if (warp >= N_POS + N_NEG) return;
    int s, d;
    float* op;
    if (warp < N_POS) {
        s = pos[warp]; d = pos[N_POS + warp]; op = outpos + warp;
    } else {
        int w = warp - N_POS;
        s = neg[w]; d = neg[N_NEG + w]; op = outneg + w;
    }
    uint2 up = *(const uint2*)(yh + (size_t)s * 256 + lane * 4);
    uint2 uq = *(const uint2*)(yh + (size_t)d * 256 + 128 + lane * 4);
    float2 p0 = __half22float2(*(__half2*)&up.x), p1 = __half22float2(*(__half2*)&up.y);
    float2 q0 = __half22float2(*(__half2*)&uq.x), q1 = __half22float2(*(__half2*)&uq.y);
    float4 bb = *(const float4*)(be1 + lane * 4);
    float4 w  = *(const float4*)(We2 + lane * 4);
    float sum = fmaxf(p0.x + q0.x + bb.x, 0.f) * w.x
              + fmaxf(p0.y + q0.y + bb.y, 0.f) * w.y
              + fmaxf(p1.x + q1.x + bb.z, 0.f) * w.z
              + fmaxf(p1.y + q1.y + bb.w, 0.f) * w.w;
    #pragma unroll
    for (int o = 16; o; o >>= 1) sum += __shfl_xor_sync(0xFFFFFFFFu, sum, o);
    if (lane == 0) *op = 1.0f / (1.0f + expf(-(sum + be2[0])));
}

// ---------------- host launcher ----------------
extern "C" void kernel_launch(void* const* d_in, const int* in_sizes, int n_in,
                              void* d_out, int out_size) {
    const float* x   = (const float*)d_in[0];
    const int*   ei  = (const int*)d_in[1];
    const int*   pos = (const int*)d_in[2];
    const int*   neg = (const int*)d_in[3];
    const float* Wl1 = (const float*)d_in[4];
    const float* bl1 = (const float*)d_in[5];
    const float* Wr1 = (const float*)d_in[6];
    const float* g1  = (const float*)d_in[7];
    const float* b1  = (const float*)d_in[8];
    const float* Wl2 = (const float*)d_in[9];
    const float* bl2 = (const float*)d_in[10];
    const float* Wr2 = (const float*)d_in[11];
    const float* g2  = (const float*)d_in[12];
    const float* b2  = (const float*)d_in[13];
    const float* Wl3 = (const float*)d_in[14];
    const float* bl3 = (const float*)d_in[15];
    const float* Wr3 = (const float*)d_in[16];
    const float* We1 = (const float*)d_in[17];
    const float* be1 = (const float*)d_in[18];
    const float* We2 = (const float*)d_in[19];
    const float* be2 = (const float*)d_in[20];

    float* out    = (float*)d_out;
    float* z      = out;
    float* outpos = out + (size_t)N_NODES * OUT_C;
    float* outneg = outpos + N_POS;

    __half *yh, *yrh, *hA, *hB, *wt;
    cudaGetSymbolAddress((void**)&yh, g_yh);
    cudaGetSymbolAddress((void**)&yrh, g_yrh);
    cudaGetSymbolAddress((void**)&hA, g_hA);
    cudaGetSymbolAddress((void**)&hB, g_hB);
    cudaGetSymbolAddress((void**)&wt, g_wth);
    __half* wt1 = wt + WT1_OFF;
    __half* wt2 = wt + WT2_OFF;
    __half* wt3 = wt + WT3_OFF;
    __half* wt4 = wt + WT4_OFF;

    const int SM128 = 2 * 128 * (128 + 8) * 2;  // 69632
    const int SM64  = 2 * 128 * (64 + 8) * 2;   // 36864
    cudaFuncSetAttribute(k_mma<128, float>,  cudaFuncAttributeMaxDynamicSharedMemorySize, SM128);
    cudaFuncSetAttribute(k_mma<128, __half>, cudaFuncAttributeMaxDynamicSharedMemorySize, SM128);
    cudaFuncSetAttribute(k_mma<64, __half>,  cudaFuncAttributeMaxDynamicSharedMemorySize, SM64);

    const int EB = (N_EDGES + 255) / 256;
    const int SCAN_NB = (N_NODES + 1023) / 1024;
    const int GT = (N_NODES + 127) / 128;
    const int AGGB = (N_NODES * 32 + 255) / 256;

    // ---- CSR build + weight prep (counts pre-zeroed by previous execution) ----
    k_prep_count<<<EB, 256>>>(ei + N_EDGES, Wl1, Wr1, Wl2, Wr2, Wl3, Wr3, We1);
    k_scan1<<<SCAN_NB, 1024>>>();
    k_scan3<<<SCAN_NB, 1024>>>();
    k_fill<<<EB, 256>>>(ei, ei + N_EDGES);

    dim3 gA(GT, 2);   // NOUT=256, two 128-col panels
    dim3 gB(GT, 1);   // NOUT=128

    // ---- layer 1: yl->yh, yr->yrh ----
    k_mma<128, float><<<gA, 256, SM128>>>(x, wt1, yh, 128, 128, yrh, 128, N_NODES);
    k_aggh<128, 1><<<AGGB, 256>>>(bl1, g1, b1, x, nullptr, hA, nullptr, yh, yrh);

    // ---- layer 2 (fp16 input) ----
    k_mma<128, __half><<<gA, 256, SM128>>>(hA, wt2, yh, 128, 128, yrh, 128, N_NODES);
    k_aggh<128, 2><<<AGGB, 256>>>(bl2, g2, b2, nullptr, hA, hB, nullptr, yh, yrh);

    // ---- layer 3 (NOUT=128); z fp32 -> d_out, z fp16 -> hA ----
    k_mma<128, __half><<<gB, 256, SM128>>>(hB, wt3, yh, 64, 64, yrh, 64, N_NODES);
    k_aggh<64, 0><<<AGGB, 256>>>(bl3, nullptr, nullptr, nullptr, nullptr, hA, z, yh, yrh);

    // ---- decode prep: P|Q from fp16 z ----
    k_mma<64, __half><<<gA, 256, SM64>>>(hA, wt4, yh, 256, 256, nullptr, 0, N_NODES);

    // ---- decode (merged pos+neg, + count reset for next execution) ----
    k_decode2<<<((N_POS + N_NEG) * 32 + 127) / 128, 128>>>(pos, neg, be1, We2, be2, outpos, outneg, yh);
}

// round 13
// speedup vs baseline: 1.0496x; 1.0161x over previous
#include <cuda_runtime.h>
#include <cuda_fp16.h>
#include <cstdint>
#include <cstddef>
#include <math.h>

#define N_NODES 100000
#define N_EDGES 1600000
#define N_POS   200000
#define N_NEG   200000
#define IN_C    128
#define HID_C   128
#define OUT_C   64
#define BN_EPS  1e-5f

// ---------------- scratch (static device globals; no allocation) ----------------
__device__ __half g_yh[N_NODES * 256];    // gathered features (fp16): yl / P|Q
__device__ __half g_yrh[N_NODES * 128];   // root-transform features (fp16)
__device__ __half g_hA[N_NODES * HID_C];  // hidden after layer 1 (fp16); reused as z_fp16
__device__ __half g_hB[N_NODES * HID_C];  // hidden after layer 2 (fp16)
__device__ __half g_wth[4 * 256 * 128];   // packed fp16 weight panels
__device__ int    g_count[N_NODES];       // zero at entry (static init + k_decode2 tail)
__device__ int    g_off[N_NODES];
__device__ int    g_cur[N_NODES];
__device__ int    g_part[256];
__device__ int    g_srcs[N_EDGES];

// Packed panel offsets (MUST match k_prep_count's layout!)
#define WT1_OFF 0          // Wl1|Wr1: 256x128
#define WT2_OFF 32768      // Wl2|Wr2: 256x128
#define WT3_OFF 65536      // Wl3|Wr3: 128x128
#define WT4_OFF 81920      // We1 top|bottom: 256x64
#define PREP_TOT 98304

// ------------- fused prep + count: weight panels + degree histogram -------------
__global__ void k_prep_count(const int* __restrict__ dst,
                             const float* __restrict__ Wl1, const float* __restrict__ Wr1,
                             const float* __restrict__ Wl2, const float* __restrict__ Wr2,
                             const float* __restrict__ Wl3, const float* __restrict__ Wr3,
                             const float* __restrict__ We1) {
    int i = blockIdx.x * 256 + threadIdx.x;
    if (i < N_EDGES) atomicAdd(&g_count[dst[i]], 1);
    if (i >= PREP_TOT) return;
    float v;
    if (i < WT3_OFF) {
        const float* s1 = (i < WT2_OFF) ? Wl1 : Wl2;
        const float* s2 = (i < WT2_OFF) ? Wr1 : Wr2;
        int j = i & 32767;
        int mm = j >> 7, kk = j & 127;
        v = (mm < 128) ? s1[(size_t)kk * 128 + mm] : s2[(size_t)kk * 128 + (mm - 128)];
    } else if (i < WT4_OFF) {
        int j = i - WT3_OFF;                   // K=128, Mh=64
        int mm = j >> 7, kk = j & 127;
        v = (mm < 64) ? Wl3[(size_t)kk * 64 + mm] : Wr3[(size_t)kk * 64 + (mm - 64)];
    } else {
        int j = i - WT4_OFF;                   // K=64, Mh=128
        int mm = j >> 6, kk = j & 63;
        const float* s1 = We1;
        const float* s2 = We1 + 64 * 128;
        v = (mm < 128) ? s1[(size_t)kk * 128 + mm] : s2[(size_t)kk * 128 + (mm - 128)];
    }
    g_wth[i] = __float2half_rn(v);
}

// ---------------- CSR scan (shfl-based block scan, 2 syncs) ----------------
__global__ void k_scan1() {
    __shared__ int wsum[32];
    int i = blockIdx.x * 1024 + threadIdx.x;
    int v = (i < N_NODES) ? g_count[i] : 0;
    int lane = threadIdx.x & 31, w = threadIdx.x >> 5;
    int x = v;
    #pragma unroll
    for (int o = 1; o < 32; o <<= 1) {
        int t = __shfl_up_sync(0xFFFFFFFFu, x, o);
        if (lane >= o) x += t;
    }
    if (lane == 31) wsum[w] = x;
    __syncthreads();
    if (w == 0) {
        int s = wsum[lane];
        #pragma unroll
        for (int o = 1; o < 32; o <<= 1) {
            int t = __shfl_up_sync(0xFFFFFFFFu, s, o);
            if (lane >= o) s += t;
        }
        wsum[lane] = s;
    }
    __syncthreads();
    int base = (w > 0) ? wsum[w - 1] : 0;
    int incl = base + x;
    if (i < N_NODES) g_off[i] = incl - v;          // exclusive prefix within block
    if (threadIdx.x == 1023) g_part[blockIdx.x] = incl;  // block total
}
__global__ void k_scan3() {
    __shared__ int red[32];
    int t = threadIdx.x, b = blockIdx.x;
    int v = (t < b) ? g_part[t] : 0;   // b <= 97 < 1024
    #pragma unroll
    for (int o = 16; o; o >>= 1) v += __shfl_xor_sync(0xFFFFFFFFu, v, o);
    if ((t & 31) == 0) red[t >> 5] = v;
    __syncthreads();
    if (t == 0) {
        int s = 0;
        #pragma unroll
        for (int w = 0; w < 32; w++) s += red[w];
        red[0] = s;
    }
    __syncthreads();
    int base = red[0];
    int i = b * 1024 + t;
    if (i < N_NODES) {
        int o = g_off[i] + base;
        g_off[i] = o;
        g_cur[i] = o;
    }
}

// ======== fp16 mma.sync m16n8k16 GEMM, 128x128 tile, 256 thr, 2 CTA/SM ========
// C[Nrows, NOUT] = A[Nrows, K] @ Wt[NOUT, K]^T; grid.y selects 128-col panel.
// cols < SPLIT -> o1 (stride S1); cols >= SPLIT -> o2 (stride S2). Both fp16.
// DOFILL: blocks with blockIdx.y == 2 instead run the CSR fill (grid-stride).
template<int K, typename AT, bool DOFILL>
__global__ __launch_bounds__(256, 2) void k_mma(const AT* __restrict__ A,
                                                const __half* __restrict__ Wt,
                                                __half* __restrict__ o1, int S1, int SPLIT,
                                                __half* __restrict__ o2, int S2,
                                                int Nrows,
                                                const int* __restrict__ esrc,
                                                const int* __restrict__ edst) {
    if (DOFILL && blockIdx.y == 2) {
        int stride = gridDim.x * 256;
        for (int i = blockIdx.x * 256 + threadIdx.x; i < N_EDGES; i += stride) {
            int d = edst[i];
            int p = atomicAdd(&g_cur[d], 1);
            g_srcs[p] = esrc[i];
        }
        return;
    }

    constexpr int SA = K + 8;
    extern __shared__ __half sh[];
    __half* As = sh;                     // [128][SA]
    __half* Bs = sh + 128 * SA;          // [128][SA]

    const int tid  = threadIdx.x;
    const int lane = tid & 31, wid = tid >> 5;
    const int gid  = lane >> 2, tg = lane & 3;
    const int mrow = (wid & 3) * 32;
    const int ncol = (wid >> 2) * 64;
    const int row0 = blockIdx.x * 128;
    const int col0 = blockIdx.y * 128;

    if (sizeof(AT) == 4) {
        #pragma unroll
        for (int l = 0; l < K / 8; l++) {
            int f = tid + l * 256;
            int r = f / (K / 4), c4 = f % (K / 4);
            int grow = row0 + r;
            float4 v = make_float4(0.f, 0.f, 0.f, 0.f);
            if (grow < Nrows) v = *(const float4*)((const float*)A + (size_t)grow * K + c4 * 4);
            __half2 h0 = __floats2half2_rn(v.x, v.y);
            __half2 h1 = __floats2half2_rn(v.z, v.w);
            uint2 u;
            u.x = *(uint32_t*)&h0;
            u.y = *(uint32_t*)&h1;
            *(uint2*)(As + r * SA + c4 * 4) = u;
        }
    } else {
        #pragma unroll
        for (int l = 0; l < K / 16; l++) {
            int f = tid + l * 256;
            int r = f / (K / 8), c8 = f % (K / 8);
            int grow = row0 + r;
            uint4 v = make_uint4(0u, 0u, 0u, 0u);
            if (grow < Nrows) v = *(const uint4*)((const __half*)A + (size_t)grow * K + c8 * 8);
            *(uint4*)(As + r * SA + c8 * 8) = v;
        }
    }
    // stage B: pure copy of this 128-col panel
    #pragma unroll
    for (int l = 0; l < K / 16; l++) {
        int f = tid + l * 256;
        int r = f / (K / 8), c8 = f % (K / 8);
        uint4 v = *(const uint4*)(Wt + (size_t)(col0 + r) * K + c8 * 8);
        *(uint4*)(Bs + r * SA + c8 * 8) = v;
    }
    __syncthreads();

    float c[2][8][4];
    #pragma unroll
    for (int mt = 0; mt < 2; mt++)
        #pragma unroll
        for (int nt = 0; nt < 8; nt++)
            #pragma unroll
            for (int j = 0; j < 4; j++) c[mt][nt][j] = 0.f;

    #pragma unroll
    for (int ks = 0; ks < K / 16; ks++) {
        const int k0 = ks * 16;
        uint32_t a[2][4];
        #pragma unroll
        for (int mt = 0; mt < 2; mt++) {
            int r = mrow + mt * 16 + gid;
            a[mt][0] = *(const uint32_t*)(As + r * SA + k0 + 2 * tg);
            a[mt][1] = *(const uint32_t*)(As + (r + 8) * SA + k0 + 2 * tg);
            a[mt][2] = *(const uint32_t*)(As + r * SA + k0 + 8 + 2 * tg);
            a[mt][3] = *(const uint32_t*)(As + (r + 8) * SA + k0 + 8 + 2 * tg);
        }
        uint32_t b[8][2];
        #pragma unroll
        for (int nt = 0; nt < 8; nt++) {
            int rn = ncol + nt * 8 + gid;
            b[nt][0] = *(const uint32_t*)(Bs + rn * SA + k0 + 2 * tg);
            b[nt][1] = *(const uint32_t*)(Bs + rn * SA + k0 + 8 + 2 * tg);
        }
        #pragma unroll
        for (int mt = 0; mt < 2; mt++)
            #pragma unroll
            for (int nt = 0; nt < 8; nt++)
                asm volatile(
                    "mma.sync.aligned.m16n8k16.row.col.f32.f16.f16.f32 "
                    "{%0,%1,%2,%3}, {%4,%5,%6,%7}, {%8,%9}, {%0,%1,%2,%3};"
                    : "+f"(c[mt][nt][0]), "+f"(c[mt][nt][1]),
                      "+f"(c[mt][nt][2]), "+f"(c[mt][nt][3])
                    : "r"(a[mt][0]), "r"(a[mt][1]), "r"(a[mt][2]), "r"(a[mt][3]),
                      "r"(b[nt][0]), "r"(b[nt][1]));
    }

    #pragma unroll
    for (int mt = 0; mt < 2; mt++) {
        int r0 = row0 + mrow + mt * 16 + gid;
        int r1 = r0 + 8;
        #pragma unroll
        for (int nt = 0; nt < 8; nt++) {
            int colg = col0 + ncol + nt * 8 + 2 * tg;
            __half2 v0 = __halves2half2(__float2half_rn(c[mt][nt][0]), __float2half_rn(c[mt][nt][1]));
            __half2 v1 = __halves2half2(__float2half_rn(c[mt][nt][2]), __float2half_rn(c[mt][nt][3]));
            if (colg < SPLIT) {
                if (r0 < Nrows) *(__half2*)(o1 + (size_t)r0 * S1 + colg) = v0;
                if (r1 < Nrows) *(__half2*)(o1 + (size_t)r1 * S1 + colg) = v1;
            } else {
                int cf = colg - SPLIT;
                if (r0 < Nrows) *(__half2*)(o2 + (size_t)r0 * S2 + cf) = v0;
                if (r1 < Nrows) *(__half2*)(o2 + (size_t)r1 * S2 + cf) = v1;
            }
        }
    }
}

// ---------------- fused aggregation + combine (warp per node, fp16 gather) ------
// RES: 0 = no BN/ReLU/residual: writes outF (fp32 z) AND outH (fp16 z copy)
//      1 = fp32 residual -> outH ; 2 = fp16 residual -> outH
template<int C, int RES>
__global__ __launch_bounds__(256) void k_aggh(const float* __restrict__ bl,
                                              const float* __restrict__ gam,
                                              const float* __restrict__ bet,
                                              const float* __restrict__ hinF,
                                              const __half* __restrict__ hinH,
                                              __half* __restrict__ outH,
                                              float* __restrict__ outF,
                                              const __half* __restrict__ yh,
                                              const __half* __restrict__ yrh) {
    constexpr int V = C / 32;
    int warp = (blockIdx.x * 256 + threadIdx.x) >> 5;
    int lane = threadIdx.x & 31;
    if (warp >= N_NODES) return;
    int n = warp;
    int beg = g_off[n], cnt = g_count[n];

    float acc[V];
    #pragma unroll
    for (int j = 0; j < V; j++) acc[j] = 0.f;

    for (int e0 = 0; e0 < cnt; e0 += 32) {
        int m = min(32, cnt - e0);
        int myidx = (lane < m) ? __ldg(&g_srcs[beg + e0 + lane]) : 0;
        int i = 0;
        for (; i + 4 <= m; i += 4) {
            int s0 = __shfl_sync(0xFFFFFFFFu, myidx, i);
            int s1 = __shfl_sync(0xFFFFFFFFu, myidx, i + 1);
            int s2 = __shfl_sync(0xFFFFFFFFu, myidx, i + 2);
            int s3 = __shfl_sync(0xFFFFFFFFu, myidx, i + 3);
            if (V == 4) {
                uint2 u0 = *(const uint2*)(yh + (size_t)s0 * C + lane * 4);
                uint2 u1 = *(const uint2*)(yh + (size_t)s1 * C + lane * 4);
                uint2 u2 = *(const uint2*)(yh + (size_t)s2 * C + lane * 4);
                uint2 u3 = *(const uint2*)(yh + (size_t)s3 * C + lane * 4);
                float2 a0 = __half22float2(*(__half2*)&u0.x), b0 = __half22float2(*(__half2*)&u0.y);
                float2 a1 = __half22float2(*(__half2*)&u1.x), b1 = __half22float2(*(__half2*)&u1.y);
                float2 a2 = __half22float2(*(__half2*)&u2.x), b2 = __half22float2(*(__half2*)&u2.y);
                float2 a3 = __half22float2(*(__half2*)&u3.x), b3 = __half22float2(*(__half2*)&u3.y);
                acc[0] += a0.x + a1.x + a2.x + a3.x;
                acc[1] += a0.y + a1.y + a2.y + a3.y;
                acc[2] += b0.x + b1.x + b2.x + b3.x;
                acc[3] += b0.y + b1.y + b2.y + b3.y;
            } else {
                uint32_t u0 = *(const uint32_t*)(yh + (size_t)s0 * C + lane * 2);
                uint32_t u1 = *(const uint32_t*)(yh + (size_t)s1 * C + lane * 2);
                uint32_t u2 = *(const uint32_t*)(yh + (size_t)s2 * C + lane * 2);
                uint32_t u3 = *(const uint32_t*)(yh + (size_t)s3 * C + lane * 2);
                float2 a0 = __half22float2(*(__half2*)&u0);
                float2 a1 = __half22float2(*(__half2*)&u1);
                float2 a2 = __half22float2(*(__half2*)&u2);
                float2 a3 = __half22float2(*(__half2*)&u3);
                acc[0] += a0.x + a1.x + a2.x + a3.x;
                acc[1] += a0.y + a1.y + a2.y + a3.y;
            }
        }
        for (; i < m; i++) {
            int s = __shfl_sync(0xFFFFFFFFu, myidx, i);
            if (V == 4) {
                uint2 u = *(const uint2*)(yh + (size_t)s * C + lane * 4);
                float2 a = __half22float2(*(__half2*)&u.x), b = __half22float2(*(__half2*)&u.y);
                acc[0] += a.x; acc[1] += a.y; acc[2] += b.x; acc[3] += b.y;
            } else {
                uint32_t u = *(const uint32_t*)(yh + (size_t)s * C + lane * 2);
                float2 a = __half22float2(*(__half2*)&u);
                acc[0] += a.x; acc[1] += a.y;
            }
        }
    }
    float inv = 1.0f / fmaxf((float)cnt, 1.0f);

    float o[V];
    {
        if (V == 4) {
            uint2 u = *(const uint2*)(yrh + (size_t)n * C + lane * 4);
            float2 a = __half22float2(*(__half2*)&u.x), b = __half22float2(*(__half2*)&u.y);
            o[0] = acc[0] * inv + bl[lane * 4 + 0] + a.x;
            o[1] = acc[1] * inv + bl[lane * 4 + 1] + a.y;
            o[2] = acc[2] * inv + bl[lane * 4 + 2] + b.x;
            o[3] = acc[3] * inv + bl[lane * 4 + 3] + b.y;
        } else {
            uint32_t u = *(const uint32_t*)(yrh + (size_t)n * C + lane * 2);
            float2 a = __half22float2(*(__half2*)&u);
            o[0] = acc[0] * inv + bl[lane * 2 + 0] + a.x;
            o[1] = acc[1] * inv + bl[lane * 2 + 1] + a.y;
        }
    }
    if (RES != 0) {
        const float s = rsqrtf(1.0f + BN_EPS);
        float h[V];
        if (RES == 1) {
            const float* hp = hinF + (size_t)n * C + lane * V;
            #pragma unroll
            for (int j = 0; j < V; j++) h[j] = hp[j];
        } else {
            uint2 u = *(const uint2*)(hinH + (size_t)n * C + lane * 4);
            float2 a = __half22float2(*(__half2*)&u.x), b = __half22float2(*(__half2*)&u.y);
            h[0] = a.x; h[1] = a.y; h[2] = b.x; h[3] = b.y;
        }
        #pragma unroll
        for (int j = 0; j < V; j++) {
            int ch = lane * V + j;
            o[j] = fmaxf(o[j] * (gam[ch] * s) + bet[ch], 0.f) + h[j];
        }
        if (V == 4) {
            __half2 h0 = __floats2half2_rn(o[0], o[1]);
            __half2 h1 = __floats2half2_rn(o[2], o[3]);
            uint2 u;
            u.x = *(uint32_t*)&h0;
            u.y = *(uint32_t*)&h1;
            *(uint2*)(outH + (size_t)n * C + lane * 4) = u;
        } else {
            __half2 h0 = __floats2half2_rn(o[0], o[1]);
            *(uint32_t*)(outH + (size_t)n * C + lane * 2) = *(uint32_t*)&h0;
        }
    } else {
        // fp32 z output + fp16 z copy (feeds fp16 decode GEMM)
        if (V == 4) {
            *(float4*)(outF + (size_t)n * C + lane * 4) = make_float4(o[0], o[1], o[2], o[3]);
            __half2 h0 = __floats2half2_rn(o[0], o[1]);
            __half2 h1 = __floats2half2_rn(o[2], o[3]);
            uint2 u;
            u.x = *(uint32_t*)&h0;
            u.y = *(uint32_t*)&h1;
            *(uint2*)(outH + (size_t)n * C + lane * 4) = u;
        } else {
            *(float2*)(outF + (size_t)n * C + lane * 2) = make_float2(o[0], o[1]);
            __half2 h0 = __floats2half2_rn(o[0], o[1]);
            *(uint32_t*)(outH + (size_t)n * C + lane * 2) = *(uint32_t*)&h0;
        }
    }
}

// ---------------- merged edge decode (pos + neg) + g_count reset ---------------
__global__ void k_decode2(const int* __restrict__ pos, const int* __restrict__ neg,
                          const float* __restrict__ be1,
                          const float* __restrict__ We2, const float* __restrict__ be2,
                          float* __restrict__ outpos, float* __restrict__ outneg,
                          const __half* __restrict__ yh) {
    int gidx = blockIdx.x * blockDim.x + threadIdx.x;
    if (gidx < N_NODES) g_count[gidx] = 0;   // reset for next execution (replay-idempotent)
    int warp = gidx >> 5;
    int lane = threadIdx.x & 31;
    if (warp >= N_POS + N_NEG) return;
    int s, d;
    float* op;
    if (warp < N_POS) {
        s = pos[warp]; d = pos[N_POS + warp]; op = outpos + warp;
    } else {
        int w = warp - N_POS;
        s = neg[w]; d = neg[N_NEG + w]; op = outneg + w;
    }
    uint2 up = *(const uint2*)(yh + (size_t)s * 256 + lane * 4);
    uint2 uq = *(const uint2*)(yh + (size_t)d * 256 + 128 + lane * 4);
    float2 p0 = __half22float2(*(__half2*)&up.x), p1 = __half22float2(*(__half2*)&up.y);
    float2 q0 = __half22float2(*(__half2*)&uq.x), q1 = __half22float2(*(__half2*)&uq.y);
    float4 bb = *(const float4*)(be1 + lane * 4);
    float4 w  = *(const float4*)(We2 + lane * 4);
    float sum = fmaxf(p0.x + q0.x + bb.x, 0.f) * w.x
              + fmaxf(p0.y + q0.y + bb.y, 0.f) * w.y
              + fmaxf(p1.x + q1.x + bb.z, 0.f) * w.z
              + fmaxf(p1.y + q1.y + bb.w, 0.f) * w.w;
    #pragma unroll
    for (int o = 16; o; o >>= 1) sum += __shfl_xor_sync(0xFFFFFFFFu, sum, o);
    if (lane == 0) *op = 1.0f / (1.0f + expf(-(sum + be2[0])));
}

// ---------------- host launcher ----------------
extern "C" void kernel_launch(void* const* d_in, const int* in_sizes, int n_in,
                              void* d_out, int out_size) {
    const float* x   = (const float*)d_in[0];
    const int*   ei  = (const int*)d_in[1];
    const int*   pos = (const int*)d_in[2];
    const int*   neg = (const int*)d_in[3];
    const float* Wl1 = (const float*)d_in[4];
    const float* bl1 = (const float*)d_in[5];
    const float* Wr1 = (const float*)d_in[6];
    const float* g1  = (const float*)d_in[7];
    const float* b1  = (const float*)d_in[8];
    const float* Wl2 = (const float*)d_in[9];
    const float* bl2 = (const float*)d_in[10];
    const float* Wr2 = (const float*)d_in[11];
    const float* g2  = (const float*)d_in[12];
    const float* b2  = (const float*)d_in[13];
    const float* Wl3 = (const float*)d_in[14];
    const float* bl3 = (const float*)d_in[15];
    const float* Wr3 = (const float*)d_in[16];
    const float* We1 = (const float*)d_in[17];
    const float* be1 = (const float*)d_in[18];
    const float* We2 = (const float*)d_in[19];
    const float* be2 = (const float*)d_in[20];

    float* out    = (float*)d_out;
    float* z      = out;
    float* outpos = out + (size_t)N_NODES * OUT_C;
    float* outneg = outpos + N_POS;

    __half *yh, *yrh, *hA, *hB, *wt;
    cudaGetSymbolAddress((void**)&yh, g_yh);
    cudaGetSymbolAddress((void**)&yrh, g_yrh);
    cudaGetSymbolAddress((void**)&hA, g_hA);
    cudaGetSymbolAddress((void**)&hB, g_hB);
    cudaGetSymbolAddress((void**)&wt, g_wth);
    __half* wt1 = wt + WT1_OFF;
    __half* wt2 = wt + WT2_OFF;
    __half* wt3 = wt + WT3_OFF;
    __half* wt4 = wt + WT4_OFF;

    const int SM128 = 2 * 128 * (128 + 8) * 2;  // 69632
    const int SM64  = 2 * 128 * (64 + 8) * 2;   // 36864
    cudaFuncSetAttribute(k_mma<128, float, true>,   cudaFuncAttributeMaxDynamicSharedMemorySize, SM128);
    cudaFuncSetAttribute(k_mma<128, __half, false>, cudaFuncAttributeMaxDynamicSharedMemorySize, SM128);
    cudaFuncSetAttribute(k_mma<64, __half, false>,  cudaFuncAttributeMaxDynamicSharedMemorySize, SM64);

    const int EB = (N_EDGES + 255) / 256;
    const int SCAN_NB = (N_NODES + 1023) / 1024;
    const int GT = (N_NODES + 127) / 128;
    const int AGGB = (N_NODES * 32 + 255) / 256;

    // ---- CSR count + weight prep (counts pre-zeroed by previous execution) ----
    k_prep_count<<<EB, 256>>>(ei + N_EDGES, Wl1, Wr1, Wl2, Wr2, Wl3, Wr3, We1);
    k_scan1<<<SCAN_NB, 1024>>>();
    k_scan3<<<SCAN_NB, 1024>>>();

    dim3 gA(GT, 2);    // NOUT=256, two 128-col panels
    dim3 gAF(GT, 3);   // + fill blocks (y==2)
    dim3 gB(GT, 1);    // NOUT=128

    // ---- layer 1 GEMM (+ CSR fill hidden in the same launch) ----
    k_mma<128, float, true><<<gAF, 256, SM128>>>(x, wt1, yh, 128, 128, yrh, 128, N_NODES,
                                                 ei, ei + N_EDGES);
    k_aggh<128, 1><<<AGGB, 256>>>(bl1, g1, b1, x, nullptr, hA, nullptr, yh, yrh);

    // ---- layer 2 (fp16 input) ----
    k_mma<128, __half, false><<<gA, 256, SM128>>>(hA, wt2, yh, 128, 128, yrh, 128, N_NODES,
                                                  nullptr, nullptr);
    k_aggh<128, 2><<<AGGB, 256>>>(bl2, g2, b2, nullptr, hA, hB, nullptr, yh, yrh);

    // ---- layer 3 (NOUT=128); z fp32 -> d_out, z fp16 -> hA ----
    k_mma<128, __half, false><<<gB, 256, SM128>>>(hB, wt3, yh, 64, 64, yrh, 64, N_NODES,
                                                  nullptr, nullptr);
    k_aggh<64, 0><<<AGGB, 256>>>(bl3, nullptr, nullptr, nullptr, nullptr, hA, z, yh, yrh);

    // ---- decode prep: P|Q from fp16 z ----
    k_mma<64, __half, false><<<gA, 256, SM64>>>(hA, wt4, yh, 256, 256, nullptr, 0, N_NODES,
                                                nullptr, nullptr);

    // ---- decode (merged pos+neg, + count reset for next execution) ----
    k_decode2<<<((N_POS + N_NEG) * 32 + 127) / 128, 128>>>(pos, neg, be1, We2, be2, outpos, outneg, yh);
}

// round 14
// speedup vs baseline: 1.0714x; 1.0207x over previous
#include <cuda_runtime.h>
#include <cuda_fp16.h>
#include <cstdint>
#include <cstddef>
#include <math.h>

#define N_NODES 100000
#define N_EDGES 1600000
#define N_POS   200000
#define N_NEG   200000
#define IN_C    128
#define HID_C   128
#define OUT_C   64
#define BN_EPS  1e-5f

// ---------------- scratch (static device globals; no allocation) ----------------
__device__ __half g_yh[N_NODES * 256];    // gathered features (fp16): yl / P|Q
__device__ __half g_yrh[N_NODES * 128];   // root-transform features (fp16)
__device__ __half g_hA[N_NODES * HID_C];  // hidden after layer 1 (fp16); reused as z_fp16
__device__ __half g_hB[N_NODES * HID_C];  // hidden after layer 2 (fp16)
__device__ __half g_wth[4 * 256 * 128];   // packed fp16 weight panels (K-MAJOR: [k][m])
__device__ int    g_count[N_NODES];       // zero at entry (static init + k_decode2 tail)
__device__ int    g_off[N_NODES];
__device__ int    g_cur[N_NODES];
__device__ int    g_part[256];
__device__ int    g_srcs[N_EDGES];

// Packed panel offsets, K-major layouts (MUST match k_prep_count!)
#define WT1_OFF 0          // [128][256] : row k = [Wl1[k][:] | Wr1[k][:]]
#define WT2_OFF 32768      // [128][256]
#define WT3_OFF 65536      // [128][128] : row k = [Wl3[k][:] | Wr3[k][:]]
#define WT4_OFF 81920      // [64][256]  : row k = [We1[k][:] | We1[64+k][:]]
#define PREP_TOT 98304

__device__ __forceinline__ uint32_t smem_u32(const void* p) {
    return (uint32_t)__cvta_generic_to_shared(p);
}

// ------------- fused prep + count: K-major panels (fully coalesced) -------------
__global__ void k_prep_count(const int* __restrict__ dst,
                             const float* __restrict__ Wl1, const float* __restrict__ Wr1,
                             const float* __restrict__ Wl2, const float* __restrict__ Wr2,
                             const float* __restrict__ Wl3, const float* __restrict__ Wr3,
                             const float* __restrict__ We1) {
    int i = blockIdx.x * 256 + threadIdx.x;
    if (i < N_EDGES) atomicAdd(&g_count[dst[i]], 1);
    if (i >= PREP_TOT) return;
    float v;
    if (i < WT3_OFF) {
        const float* s1 = (i < WT2_OFF) ? Wl1 : Wl2;
        const float* s2 = (i < WT2_OFF) ? Wr1 : Wr2;
        int j = i & 32767;
        int kk = j >> 8, mm = j & 255;
        v = (mm < 128) ? s1[(size_t)kk * 128 + mm] : s2[(size_t)kk * 128 + (mm - 128)];
    } else if (i < WT4_OFF) {
        int j = i - WT3_OFF;
        int kk = j >> 7, mm = j & 127;
        v = (mm < 64) ? Wl3[(size_t)kk * 64 + mm] : Wr3[(size_t)kk * 64 + (mm - 64)];
    } else {
        int j = i - WT4_OFF;
        int kk = j >> 8, mm = j & 255;
        v = (mm < 128) ? We1[(size_t)kk * 128 + mm]
                       : We1[(size_t)(64 + kk) * 128 + (mm - 128)];
    }
    g_wth[i] = __float2half_rn(v);
}

// ---------------- CSR scan (shfl-based block scan, 2 syncs) ----------------
__global__ void k_scan1() {
    __shared__ int wsum[32];
    int i = blockIdx.x * 1024 + threadIdx.x;
    int v = (i < N_NODES) ? g_count[i] : 0;
    int lane = threadIdx.x & 31, w = threadIdx.x >> 5;
    int x = v;
    #pragma unroll
    for (int o = 1; o < 32; o <<= 1) {
        int t = __shfl_up_sync(0xFFFFFFFFu, x, o);
        if (lane >= o) x += t;
    }
    if (lane == 31) wsum[w] = x;
    __syncthreads();
    if (w == 0) {
        int s = wsum[lane];
        #pragma unroll
        for (int o = 1; o < 32; o <<= 1) {
            int t = __shfl_up_sync(0xFFFFFFFFu, s, o);
            if (lane >= o) s += t;
        }
        wsum[lane] = s;
    }
    __syncthreads();
    int base = (w > 0) ? wsum[w - 1] : 0;
    int incl = base + x;
    if (i < N_NODES) g_off[i] = incl - v;
    if (threadIdx.x == 1023) g_part[blockIdx.x] = incl;
}
__global__ void k_scan3() {
    __shared__ int red[32];
    int t = threadIdx.x, b = blockIdx.x;
    int v = (t < b) ? g_part[t] : 0;
    #pragma unroll
    for (int o = 16; o; o >>= 1) v += __shfl_xor_sync(0xFFFFFFFFu, v, o);
    if ((t & 31) == 0) red[t >> 5] = v;
    __syncthreads();
    if (t == 0) {
        int s = 0;
        #pragma unroll
        for (int w = 0; w < 32; w++) s += red[w];
        red[0] = s;
    }
    __syncthreads();
    int base = red[0];
    int i = b * 1024 + t;
    if (i < N_NODES) {
        int o = g_off[i] + base;
        g_off[i] = o;
        g_cur[i] = o;
    }
}

// ======== fp16 mma.sync m16n8k16 GEMM, 128x128 tile, ldmatrix fragments ========
// C[Nrows, NOUT] = A[Nrows, K] @ W_kmajor[K, NOUT]; panel = 128 cols.
// A smem [m][K+8]; B smem K-major [k][136] -> b frags via ldmatrix.trans.
// DOFILL: 1D grid, bid%3==2 -> CSR fill (interleaved with GEMM blocks).
template<int K, typename AT, bool DOFILL>
__global__ __launch_bounds__(256, 2) void k_mma(const AT* __restrict__ A,
                                                const __half* __restrict__ Wt, int WS,
                                                __half* __restrict__ o1, int S1, int SPLIT,
                                                __half* __restrict__ o2, int S2,
                                                int Nrows,
                                                const int* __restrict__ esrc,
                                                const int* __restrict__ edst) {
    int row0, col0;
    if (DOFILL) {
        int bid = blockIdx.x;
        int role = bid - (bid / 3) * 3;
        if (role == 2) {
            int nblk = gridDim.x / 3;
            int stride = nblk * 256;
            for (int i = (bid / 3) * 256 + threadIdx.x; i < N_EDGES; i += stride) {
                int d = edst[i];
                int p = atomicAdd(&g_cur[d], 1);
                g_srcs[p] = esrc[i];
            }
            return;
        }
        row0 = (bid / 3) * 128;
        col0 = role * 128;
    } else {
        row0 = blockIdx.x * 128;
        col0 = blockIdx.y * 128;
    }

    constexpr int SA = K + 8;            // A stride (halves)
    constexpr int SB = 136;              // B stride (halves)
    extern __shared__ __half sh[];
    __half* As = sh;                     // [128][SA]
    __half* Bs = sh + 128 * SA;          // [K][SB]

    const int tid  = threadIdx.x;
    const int lane = tid & 31, wid = tid >> 5;
    const int gid  = lane >> 2, tg = lane & 3;
    const int mrow = (wid & 3) * 32;
    const int ncol = (wid >> 2) * 64;

    // ---- stage A ----
    if (sizeof(AT) == 4) {
        #pragma unroll
        for (int l = 0; l < K / 8; l++) {
            int f = tid + l * 256;
            int r = f / (K / 4), c4 = f % (K / 4);
            int grow = row0 + r;
            float4 v = make_float4(0.f, 0.f, 0.f, 0.f);
            if (grow < Nrows) v = *(const float4*)((const float*)A + (size_t)grow * K + c4 * 4);
            __half2 h0 = __floats2half2_rn(v.x, v.y);
            __half2 h1 = __floats2half2_rn(v.z, v.w);
            uint2 u;
            u.x = *(uint32_t*)&h0;
            u.y = *(uint32_t*)&h1;
            *(uint2*)(As + r * SA + c4 * 4) = u;
        }
    } else {
        #pragma unroll
        for (int l = 0; l < K / 16; l++) {
            int f = tid + l * 256;
            int r = f / (K / 8), c8 = f % (K / 8);
            int grow = row0 + r;
            uint4 v = make_uint4(0u, 0u, 0u, 0u);
            if (grow < Nrows) v = *(const uint4*)((const __half*)A + (size_t)grow * K + c8 * 8);
            *(uint4*)(As + r * SA + c8 * 8) = v;
        }
    }
    // ---- stage B (K-major, pure uint4 copy): K rows x 128 halves ----
    #pragma unroll
    for (int l = 0; l < K / 16; l++) {
        int f = tid + l * 256;
        int k = f >> 4, c8 = f & 15;
        uint4 v = *(const uint4*)(Wt + (size_t)k * WS + col0 + c8 * 8);
        *(uint4*)(Bs + k * SB + c8 * 8) = v;
    }
    __syncthreads();

    // ---- per-thread ldmatrix base addresses (bytes, shared space) ----
    const int t8 = lane & 7, thi = (lane >> 3) & 1, tn = lane >> 4;
    const uint32_t As_addr = smem_u32(As);
    const uint32_t Bs_addr = smem_u32(Bs);
    // A tiles: t0 rows+0 klo, t1 rows+8 klo, t2 rows+0 khi, t3 rows+8 khi
    const uint32_t aaddr0 = As_addr + (uint32_t)(((mrow + t8 + thi * 8) * SA + tn * 8) * 2);
    // B tiles: t0 klo n0, t1 khi n0, t2 klo n0+8, t3 khi n0+8
    const uint32_t baddr0 = Bs_addr + (uint32_t)(((t8 + thi * 8) * SB + ncol + tn * 8) * 2);

    float c[2][8][4];
    #pragma unroll
    for (int mt = 0; mt < 2; mt++)
        #pragma unroll
        for (int nt = 0; nt < 8; nt++)
            #pragma unroll
            for (int j = 0; j < 4; j++) c[mt][nt][j] = 0.f;

    #pragma unroll
    for (int ks = 0; ks < K / 16; ks++) {
        uint32_t a[2][4];
        #pragma unroll
        for (int mt = 0; mt < 2; mt++) {
            uint32_t addr = aaddr0 + (uint32_t)((mt * 16 * SA + ks * 16) * 2);
            asm volatile("ldmatrix.sync.aligned.m8n8.x4.shared.b16 {%0,%1,%2,%3}, [%4];"
                : "=r"(a[mt][0]), "=r"(a[mt][1]), "=r"(a[mt][2]), "=r"(a[mt][3])
                : "r"(addr));
        }
        uint32_t b[8][2];
        #pragma unroll
        for (int j = 0; j < 4; j++) {
            uint32_t addr = baddr0 + (uint32_t)((ks * 16 * SB + j * 16) * 2);
            asm volatile("ldmatrix.sync.aligned.m8n8.x4.trans.shared.b16 {%0,%1,%2,%3}, [%4];"
                : "=r"(b[2 * j][0]), "=r"(b[2 * j][1]),
                  "=r"(b[2 * j + 1][0]), "=r"(b[2 * j + 1][1])
                : "r"(addr));
        }
        #pragma unroll
        for (int mt = 0; mt < 2; mt++)
            #pragma unroll
            for (int nt = 0; nt < 8; nt++)
                asm volatile(
                    "mma.sync.aligned.m16n8k16.row.col.f32.f16.f16.f32 "
                    "{%0,%1,%2,%3}, {%4,%5,%6,%7}, {%8,%9}, {%0,%1,%2,%3};"
                    : "+f"(c[mt][nt][0]), "+f"(c[mt][nt][1]),
                      "+f"(c[mt][nt][2]), "+f"(c[mt][nt][3])
                    : "r"(a[mt][0]), "r"(a[mt][1]), "r"(a[mt][2]), "r"(a[mt][3]),
                      "r"(b[nt][0]), "r"(b[nt][1]));
    }

    #pragma unroll
    for (int mt = 0; mt < 2; mt++) {
        int r0 = row0 + mrow + mt * 16 + gid;
        int r1 = r0 + 8;
        #pragma unroll
        for (int nt = 0; nt < 8; nt++) {
            int colg = col0 + ncol + nt * 8 + 2 * tg;
            __half2 v0 = __halves2half2(__float2half_rn(c[mt][nt][0]), __float2half_rn(c[mt][nt][1]));
            __half2 v1 = __halves2half2(__float2half_rn(c[mt][nt][2]), __float2half_rn(c[mt][nt][3]));
            if (colg < SPLIT) {
                if (r0 < Nrows) *(__half2*)(o1 + (size_t)r0 * S1 + colg) = v0;
                if (r1 < Nrows) *(__half2*)(o1 + (size_t)r1 * S1 + colg) = v1;
            } else {
                int cf = colg - SPLIT;
                if (r0 < Nrows) *(__half2*)(o2 + (size_t)r0 * S2 + cf) = v0;
                if (r1 < Nrows) *(__half2*)(o2 + (size_t)r1 * S2 + cf) = v1;
            }
        }
    }
}

// ---------------- fused aggregation + combine (warp per node, fp16 gather) ------
template<int C, int RES>
__global__ __launch_bounds__(256) void k_aggh(const float* __restrict__ bl,
                                              const float* __restrict__ gam,
                                              const float* __restrict__ bet,
                                              const float* __restrict__ hinF,
                                              const __half* __restrict__ hinH,
                                              __half* __restrict__ outH,
                                              float* __restrict__ outF,
                                              const __half* __restrict__ yh,
                                              const __half* __restrict__ yrh) {
    constexpr int V = C / 32;
    int warp = (blockIdx.x * 256 + threadIdx.x) >> 5;
    int lane = threadIdx.x & 31;
    if (warp >= N_NODES) return;
    int n = warp;
    int beg = g_off[n], cnt = g_count[n];

    float acc[V];
    #pragma unroll
    for (int j = 0; j < V; j++) acc[j] = 0.f;

    for (int e0 = 0; e0 < cnt; e0 += 32) {
        int m = min(32, cnt - e0);
        int myidx = (lane < m) ? __ldg(&g_srcs[beg + e0 + lane]) : 0;
        int i = 0;
        for (; i + 4 <= m; i += 4) {
            int s0 = __shfl_sync(0xFFFFFFFFu, myidx, i);
            int s1 = __shfl_sync(0xFFFFFFFFu, myidx, i + 1);
            int s2 = __shfl_sync(0xFFFFFFFFu, myidx, i + 2);
            int s3 = __shfl_sync(0xFFFFFFFFu, myidx, i + 3);
            if (V == 4) {
                uint2 u0 = *(const uint2*)(yh + (size_t)s0 * C + lane * 4);
                uint2 u1 = *(const uint2*)(yh + (size_t)s1 * C + lane * 4);
                uint2 u2 = *(const uint2*)(yh + (size_t)s2 * C + lane * 4);
                uint2 u3 = *(const uint2*)(yh + (size_t)s3 * C + lane * 4);
                float2 a0 = __half22float2(*(__half2*)&u0.x), b0 = __half22float2(*(__half2*)&u0.y);
                float2 a1 = __half22float2(*(__half2*)&u1.x), b1 = __half22float2(*(__half2*)&u1.y);
                float2 a2 = __half22float2(*(__half2*)&u2.x), b2 = __half22float2(*(__half2*)&u2.y);
                float2 a3 = __half22float2(*(__half2*)&u3.x), b3 = __half22float2(*(__half2*)&u3.y);
                acc[0] += a0.x + a1.x + a2.x + a3.x;
                acc[1] += a0.y + a1.y + a2.y + a3.y;
                acc[2] += b0.x + b1.x + b2.x + b3.x;
                acc[3] += b0.y + b1.y + b2.y + b3.y;
            } else {
                uint32_t u0 = *(const uint32_t*)(yh + (size_t)s0 * C + lane * 2);
                uint32_t u1 = *(const uint32_t*)(yh + (size_t)s1 * C + lane * 2);
                uint32_t u2 = *(const uint32_t*)(yh + (size_t)s2 * C + lane * 2);
                uint32_t u3 = *(const uint32_t*)(yh + (size_t)s3 * C + lane * 2);
                float2 a0 = __half22float2(*(__half2*)&u0);
                float2 a1 = __half22float2(*(__half2*)&u1);
                float2 a2 = __half22float2(*(__half2*)&u2);
                float2 a3 = __half22float2(*(__half2*)&u3);
                acc[0] += a0.x + a1.x + a2.x + a3.x;
                acc[1] += a0.y + a1.y + a2.y + a3.y;
            }
        }
        for (; i < m; i++) {
            int s = __shfl_sync(0xFFFFFFFFu, myidx, i);
            if (V == 4) {
                uint2 u = *(const uint2*)(yh + (size_t)s * C + lane * 4);
                float2 a = __half22float2(*(__half2*)&u.x), b = __half22float2(*(__half2*)&u.y);
                acc[0] += a.x; acc[1] += a.y; acc[2] += b.x; acc[3] += b.y;
            } else {
                uint32_t u = *(const uint32_t*)(yh + (size_t)s * C + lane * 2);
                float2 a = __half22float2(*(__half2*)&u);
                acc[0] += a.x; acc[1] += a.y;
            }
        }
    }
    float inv = 1.0f / fmaxf((float)cnt, 1.0f);

    float o[V];
    {
        if (V == 4) {
            uint2 u = *(const uint2*)(yrh + (size_t)n * C + lane * 4);
            float2 a = __half22float2(*(__half2*)&u.x), b = __half22float2(*(__half2*)&u.y);
            o[0] = acc[0] * inv + bl[lane * 4 + 0] + a.x;
            o[1] = acc[1] * inv + bl[lane * 4 + 1] + a.y;
            o[2] = acc[2] * inv + bl[lane * 4 + 2] + b.x;
            o[3] = acc[3] * inv + bl[lane * 4 + 3] + b.y;
        } else {
            uint32_t u = *(const uint32_t*)(yrh + (size_t)n * C + lane * 2);
            float2 a = __half22float2(*(__half2*)&u);
            o[0] = acc[0] * inv + bl[lane * 2 + 0] + a.x;
            o[1] = acc[1] * inv + bl[lane * 2 + 1] + a.y;
        }
    }
    if (RES != 0) {
        const float s = rsqrtf(1.0f + BN_EPS);
        float h[V];
        if (RES == 1) {
            const float* hp = hinF + (size_t)n * C + lane * V;
            #pragma unroll
            for (int j = 0; j < V; j++) h[j] = hp[j];
        } else {
            uint2 u = *(const uint2*)(hinH + (size_t)n * C + lane * 4);
            float2 a = __half22float2(*(__half2*)&u.x), b = __half22float2(*(__half2*)&u.y);
            h[0] = a.x; h[1] = a.y; h[2] = b.x; h[3] = b.y;
        }
        #pragma unroll
        for (int j = 0; j < V; j++) {
            int ch = lane * V + j;
            o[j] = fmaxf(o[j] * (gam[ch] * s) + bet[ch], 0.f) + h[j];
        }
        if (V == 4) {
            __half2 h0 = __floats2half2_rn(o[0], o[1]);
            __half2 h1 = __floats2half2_rn(o[2], o[3]);
            uint2 u;
            u.x = *(uint32_t*)&h0;
            u.y = *(uint32_t*)&h1;
            *(uint2*)(outH + (size_t)n * C + lane * 4) = u;
        } else {
            __half2 h0 = __floats2half2_rn(o[0], o[1]);
            *(uint32_t*)(outH + (size_t)n * C + lane * 2) = *(uint32_t*)&h0;
        }
    } else {
        if (V == 4) {
            *(float4*)(outF + (size_t)n * C + lane * 4) = make_float4(o[0], o[1], o[2], o[3]);
            __half2 h0 = __floats2half2_rn(o[0], o[1]);
            __half2 h1 = __floats2half2_rn(o[2], o[3]);
            uint2 u;
            u.x = *(uint32_t*)&h0;
            u.y = *(uint32_t*)&h1;
            *(uint2*)(outH + (size_t)n * C + lane * 4) = u;
        } else {
            *(float2*)(outF + (size_t)n * C + lane * 2) = make_float2(o[0], o[1]);
            __half2 h0 = __floats2half2_rn(o[0], o[1]);
            *(uint32_t*)(outH + (size_t)n * C + lane * 2) = *(uint32_t*)&h0;
        }
    }
}

// ---------------- merged edge decode (pos + neg) + g_count reset ---------------
__global__ void k_decode2(const int* __restrict__ pos, const int* __restrict__ neg,
                          const float* __restrict__ be1,
                          const float* __restrict__ We2, const float* __restrict__ be2,
                          float* __restrict__ outpos, float* __restrict__ outneg,
                          const __half* __restrict__ yh) {
    int gidx = blockIdx.x * blockDim.x + threadIdx.x;
    if (gidx < N_NODES) g_count[gidx] = 0;
    int warp = gidx >> 5;
    int lane = threadIdx.x & 31;
    if (warp >= N_POS + N_NEG) return;
    int s, d;
    float* op;
    if (warp < N_POS) {
        s = pos[warp]; d = pos[N_POS + warp]; op = outpos + warp;
    } else {
        int w = warp - N_POS;
        s = neg[w]; d = neg[N_NEG + w]; op = outneg + w;
    }
    uint2 up = *(const uint2*)(yh + (size_t)s * 256 + lane * 4);
    uint2 uq = *(const uint2*)(yh + (size_t)d * 256 + 128 + lane * 4);
    float2 p0 = __half22float2(*(__half2*)&up.x), p1 = __half22float2(*(__half2*)&up.y);
    float2 q0 = __half22float2(*(__half2*)&uq.x), q1 = __half22float2(*(__half2*)&uq.y);
    float4 bb = *(const float4*)(be1 + lane * 4);
    float4 w  = *(const float4*)(We2 + lane * 4);
    float sum = fmaxf(p0.x + q0.x + bb.x, 0.f) * w.x
              + fmaxf(p0.y + q0.y + bb.y, 0.f) * w.y
              + fmaxf(p1.x + q1.x + bb.z, 0.f) * w.z
              + fmaxf(p1.y + q1.y + bb.w, 0.f) * w.w;
    #pragma unroll
    for (int o = 16; o; o >>= 1) sum += __shfl_xor_sync(0xFFFFFFFFu, sum, o);
    if (lane == 0) *op = 1.0f / (1.0f + expf(-(sum + be2[0])));
}

// ---------------- host launcher ----------------
extern "C" void kernel_launch(void* const* d_in, const int* in_sizes, int n_in,
                              void* d_out, int out_size) {
    const float* x   = (const float*)d_in[0];
    const int*   ei  = (const int*)d_in[1];
    const int*   pos = (const int*)d_in[2];
    const int*   neg = (const int*)d_in[3];
    const float* Wl1 = (const float*)d_in[4];
    const float* bl1 = (const float*)d_in[5];
    const float* Wr1 = (const float*)d_in[6];
    const float* g1  = (const float*)d_in[7];
    const float* b1  = (const float*)d_in[8];
    const float* Wl2 = (const float*)d_in[9];
    const float* bl2 = (const float*)d_in[10];
    const float* Wr2 = (const float*)d_in[11];
    const float* g2  = (const float*)d_in[12];
    const float* b2  = (const float*)d_in[13];
    const float* Wl3 = (const float*)d_in[14];
    const float* bl3 = (const float*)d_in[15];
    const float* Wr3 = (const float*)d_in[16];
    const float* We1 = (const float*)d_in[17];
    const float* be1 = (const float*)d_in[18];
    const float* We2 = (const float*)d_in[19];
    const float* be2 = (const float*)d_in[20];

    float* out    = (float*)d_out;
    float* z      = out;
    float* outpos = out + (size_t)N_NODES * OUT_C;
    float* outneg = outpos + N_POS;

    __half *yh, *yrh, *hA, *hB, *wt;
    cudaGetSymbolAddress((void**)&yh, g_yh);
    cudaGetSymbolAddress((void**)&yrh, g_yrh);
    cudaGetSymbolAddress((void**)&hA, g_hA);
    cudaGetSymbolAddress((void**)&hB, g_hB);
    cudaGetSymbolAddress((void**)&wt, g_wth);
    __half* wt1 = wt + WT1_OFF;
    __half* wt2 = wt + WT2_OFF;
    __half* wt3 = wt + WT3_OFF;
    __half* wt4 = wt + WT4_OFF;

    const int SM128 = (128 * (128 + 8) + 128 * 136) * 2;  // 69632
    const int SM64  = (128 * (64 + 8) + 64 * 136) * 2;    // 35840
    cudaFuncSetAttribute(k_mma<128, float, true>,   cudaFuncAttributeMaxDynamicSharedMemorySize, SM128);
    cudaFuncSetAttribute(k_mma<128, __half, false>, cudaFuncAttributeMaxDynamicSharedMemorySize, SM128);
    cudaFuncSetAttribute(k_mma<64, __half, false>,  cudaFuncAttributeMaxDynamicSharedMemorySize, SM64);

    const int EB = (N_EDGES + 255) / 256;
    const int SCAN_NB = (N_NODES + 1023) / 1024;
    const int GT = (N_NODES + 127) / 128;
    const int AGGB = (N_NODES * 32 + 255) / 256;

    // ---- CSR count + weight prep (counts pre-zeroed by previous execution) ----
    k_prep_count<<<EB, 256>>>(ei + N_EDGES, Wl1, Wr1, Wl2, Wr2, Wl3, Wr3, We1);
    k_scan1<<<SCAN_NB, 1024>>>();
    k_scan3<<<SCAN_NB, 1024>>>();

    dim3 gA(GT, 2);    // NOUT=256, two 128-col panels
    dim3 gB(GT, 1);    // NOUT=128

    // ---- layer 1 GEMM with INTERLEAVED fill blocks (1D grid, role = bid%3) ----
    k_mma<128, float, true><<<3 * GT, 256, SM128>>>(x, wt1, 256, yh, 128, 128, yrh, 128,
                                                    N_NODES, ei, ei + N_EDGES);
    k_aggh<128, 1><<<AGGB, 256>>>(bl1, g1, b1, x, nullptr, hA, nullptr, yh, yrh);

    // ---- layer 2 (fp16 input) ----
    k_mma<128, __half, false><<<gA, 256, SM128>>>(hA, wt2, 256, yh, 128, 128, yrh, 128,
                                                  N_NODES, nullptr, nullptr);
    k_aggh<128, 2><<<AGGB, 256>>>(bl2, g2, b2, nullptr, hA, hB, nullptr, yh, yrh);

    // ---- layer 3 (NOUT=128); z fp32 -> d_out, z fp16 -> hA ----
    k_mma<128, __half, false><<<gB, 256, SM128>>>(hB, wt3, 128, yh, 64, 64, yrh, 64,
                                                  N_NODES, nullptr, nullptr);
    k_aggh<64, 0><<<AGGB, 256>>>(bl3, nullptr, nullptr, nullptr, nullptr, hA, z, yh, yrh);

    // ---- decode prep: P|Q from fp16 z ----
    k_mma<64, __half, false><<<gA, 256, SM64>>>(hA, wt4, 256, yh, 256, 256, nullptr, 0,
                                                N_NODES, nullptr, nullptr);

    // ---- decode (merged pos+neg, + count reset for next execution) ----
    k_decode2<<<((N_POS + N_NEG) * 32 + 127) / 128, 128>>>(pos, neg, be1, We2, be2, outpos, outneg, yh);
}